// round 3
// baseline (speedup 1.0000x reference)
#include <cuda_runtime.h>
#include <math.h>

// Problem shapes (fixed by setup_inputs)
#define NROWS 16384   // B*S
#define DMODEL 1024
#define DFF 4096
#define TOPK 512

// Scratch (device globals: no allocations allowed)
__device__ float g_xn[(size_t)NROWS * DMODEL];       // 64 MB
__device__ float g_h [(size_t)NROWS * DMODEL];       // 64 MB
__device__ float g_sc[(size_t)NROWS * DFF];          // 256 MB
__device__ float g_z [(size_t)NROWS * DFF];          // 256 MB

// ---------------------------------------------------------------------------
// XLA f32 erf (shared CPU/GPU elemental emitter polynomial): clamp(x,-4,4);
// x*P(x^2)/Q(x^2) with separate mul/add (XLA does not contract to FMA).
// ---------------------------------------------------------------------------
__device__ __forceinline__ float erf_xla(float xin) {
    float x = fminf(fmaxf(xin, -4.0f), 4.0f);
    float x2 = __fmul_rn(x, x);
    float p = -2.72614225801306e-10f;
    p = __fadd_rn(__fmul_rn(p, x2),  2.77068142495902e-08f);
    p = __fadd_rn(__fmul_rn(p, x2), -2.10102402082508e-06f);
    p = __fadd_rn(__fmul_rn(p, x2), -5.69250639462346e-05f);
    p = __fadd_rn(__fmul_rn(p, x2), -7.34990630326855e-04f);
    p = __fadd_rn(__fmul_rn(p, x2), -2.95459980854025e-03f);
    p = __fadd_rn(__fmul_rn(p, x2), -1.60960333262415e-02f);
    float q = -1.45660718464996e-05f;
    q = __fadd_rn(__fmul_rn(q, x2), -2.13374055278905e-04f);
    q = __fadd_rn(__fmul_rn(q, x2), -1.68282697438203e-03f);
    q = __fadd_rn(__fmul_rn(q, x2), -7.37332916720468e-03f);
    q = __fadd_rn(__fmul_rn(q, x2), -1.42647390514189e-02f);
    return __fdiv_rn(__fmul_rn(x, p), q);
}

// jax.nn.gelu(approximate=False): 0.5 * x * (1 + erf(x / sqrt(2)))
__device__ __forceinline__ float gelu_f(float v) {
    float t = __fdiv_rn(v, 1.41421356237309504880f);
    float e = erf_xla(t);
    return __fmul_rn(__fmul_rn(v, __fadd_rn(e, 1.0f)), 0.5f);
}

// ---------------------------------------------------------------------------
// LayerNorm: one block per row, D=1024, 256 threads x float4.
// Statistics accumulated in fp64 (near-exact), elementwise math in f32.
// ---------------------------------------------------------------------------
__global__ void __launch_bounds__(256) ln_kernel(
    const float* __restrict__ x, const float* __restrict__ g,
    const float* __restrict__ b, float* __restrict__ o)
{
    __shared__ double red[8];
    __shared__ float s_mu, s_inv;
    const int row = blockIdx.x;
    const int tid = threadIdx.x;
    const float4* xr = (const float4*)(x + (size_t)row * DMODEL);
    float4* orow = (float4*)(o + (size_t)row * DMODEL);

    float4 v = xr[tid];

    // pass 1: mean (fp64)
    double s = (double)v.x + (double)v.y + (double)v.z + (double)v.w;
    #pragma unroll
    for (int off = 16; off; off >>= 1) s += __shfl_down_sync(0xffffffffu, s, off);
    if ((tid & 31) == 0) red[tid >> 5] = s;
    __syncthreads();
    if (tid == 0) {
        double S = 0.0;
        #pragma unroll
        for (int w = 0; w < 8; w++) S += red[w];
        s_mu = (float)(S * (1.0 / DMODEL));
    }
    __syncthreads();
    const float mu = s_mu;
    __syncthreads();

    // pass 2: variance of f32 (x - mu), accumulated in fp64
    float dx0 = __fsub_rn(v.x, mu), dx1 = __fsub_rn(v.y, mu);
    float dx2 = __fsub_rn(v.z, mu), dx3 = __fsub_rn(v.w, mu);
    double ss = (double)__fmul_rn(dx0, dx0) + (double)__fmul_rn(dx1, dx1)
              + (double)__fmul_rn(dx2, dx2) + (double)__fmul_rn(dx3, dx3);
    #pragma unroll
    for (int off = 16; off; off >>= 1) ss += __shfl_down_sync(0xffffffffu, ss, off);
    if ((tid & 31) == 0) red[tid >> 5] = ss;
    __syncthreads();
    if (tid == 0) {
        double SS = 0.0;
        #pragma unroll
        for (int w = 0; w < 8; w++) SS += red[w];
        float var = (float)(SS * (1.0 / DMODEL));
        s_inv = (float)(1.0 / sqrt((double)__fadd_rn(var, 1e-5f)));
    }
    __syncthreads();
    const float inv = s_inv;
    const float4 gv = ((const float4*)g)[tid];
    const float4 bv = ((const float4*)b)[tid];
    float4 r;
    r.x = __fadd_rn(__fmul_rn(__fmul_rn(dx0, inv), gv.x), bv.x);
    r.y = __fadd_rn(__fmul_rn(__fmul_rn(dx1, inv), gv.y), bv.y);
    r.z = __fadd_rn(__fmul_rn(__fmul_rn(dx2, inv), gv.z), bv.z);
    r.w = __fadd_rn(__fmul_rn(__fmul_rn(dx3, inv), gv.w), bv.w);
    orow[tid] = r;
}

// ---------------------------------------------------------------------------
// FAST path: C[M,N] = A[M,K] @ B[N,K]^T. 128x128 tile, Kstep 8, 256 thr,
// 8x8/thread, sequential-k FMA. Used for z and out (value-level accuracy).
// ---------------------------------------------------------------------------
__global__ void __launch_bounds__(256) gemm_bt(
    const float* __restrict__ A, const float* __restrict__ B,
    float* __restrict__ C, int M, int N, int K)
{
    __shared__ float As[8][128];
    __shared__ float Bs[8][128];

    const int m0 = blockIdx.y * 128;
    const int n0 = blockIdx.x * 128;
    const int tid = threadIdx.x;
    const int lr = tid >> 1;
    const int lc = (tid & 1) * 4;
    const int tx = tid & 15;
    const int ty = tid >> 4;

    const float* Aptr = A + (size_t)(m0 + lr) * K + lc;
    const float* Bptr = B + (size_t)(n0 + lr) * K + lc;

    float acc[8][8];
    #pragma unroll
    for (int i = 0; i < 8; i++)
        #pragma unroll
        for (int j = 0; j < 8; j++) acc[i][j] = 0.0f;

    float4 av = *(const float4*)(Aptr);
    float4 bv = *(const float4*)(Bptr);

    for (int k0 = 0; k0 < K; k0 += 8) {
        As[lc + 0][lr] = av.x; As[lc + 1][lr] = av.y;
        As[lc + 2][lr] = av.z; As[lc + 3][lr] = av.w;
        Bs[lc + 0][lr] = bv.x; Bs[lc + 1][lr] = bv.y;
        Bs[lc + 2][lr] = bv.z; Bs[lc + 3][lr] = bv.w;
        __syncthreads();

        if (k0 + 8 < K) {
            av = *(const float4*)(Aptr + k0 + 8);
            bv = *(const float4*)(Bptr + k0 + 8);
        }

        #pragma unroll
        for (int kk = 0; kk < 8; kk++) {
            float4 a0 = *(const float4*)&As[kk][ty * 4];
            float4 a1 = *(const float4*)&As[kk][64 + ty * 4];
            float4 b0 = *(const float4*)&Bs[kk][tx * 4];
            float4 b1 = *(const float4*)&Bs[kk][64 + tx * 4];
            float ar[8] = {a0.x, a0.y, a0.z, a0.w, a1.x, a1.y, a1.z, a1.w};
            float br[8] = {b0.x, b0.y, b0.z, b0.w, b1.x, b1.y, b1.z, b1.w};
            #pragma unroll
            for (int i = 0; i < 8; i++)
                #pragma unroll
                for (int j = 0; j < 8; j++)
                    acc[i][j] = fmaf(ar[i], br[j], acc[i][j]);
        }
        __syncthreads();
    }

    #pragma unroll
    for (int i = 0; i < 8; i++) {
        const int row = m0 + ((i < 4) ? (ty * 4 + i) : (64 + ty * 4 + i - 4));
        float4 lo, hi;
        lo.x = acc[i][0]; lo.y = acc[i][1]; lo.z = acc[i][2]; lo.w = acc[i][3];
        hi.x = acc[i][4]; hi.y = acc[i][5]; hi.z = acc[i][6]; hi.w = acc[i][7];
        *(float4*)(C + (size_t)row * N + n0 + tx * 4)      = lo;
        *(float4*)(C + (size_t)row * N + n0 + 64 + tx * 4) = hi;
    }
}

// ---------------------------------------------------------------------------
// ACCURATE path (router GEMMs): two-level chunked accumulation.
// Fresh fp32 chunk accumulator every 32 k-steps, folded into master acc.
// Within-chunk error ~ eps*32 instead of eps*1024 -> score deviation ~5e-8.
// 128x64 tile, 256 threads, 8x4 per thread. Optional exact-gelu epilogue.
// ---------------------------------------------------------------------------
template <bool GELU>
__global__ void __launch_bounds__(256) gemm_bt_acc(
    const float* __restrict__ A, const float* __restrict__ B,
    float* __restrict__ C, int M, int N, int K)
{
    __shared__ float As[8][128];
    __shared__ float Bs[8][64];

    const int m0 = blockIdx.y * 128;
    const int n0 = blockIdx.x * 64;
    const int tid = threadIdx.x;
    // A loads: 1024 floats/tile -> 4/thread
    const int lrA = tid >> 1;
    const int lcA = (tid & 1) * 4;
    // B loads: 512 floats/tile -> 2/thread
    const int lrB = tid >> 2;
    const int lcB = (tid & 3) * 2;
    const int tx = tid & 15;          // 16 col groups x 4 = 64
    const int ty = tid >> 4;          // 16 row groups x (4+4) = 128

    const float* Aptr = A + (size_t)(m0 + lrA) * K + lcA;
    const float* Bptr = B + (size_t)(n0 + lrB) * K + lcB;

    float acc[8][4], chk[8][4];
    #pragma unroll
    for (int i = 0; i < 8; i++)
        #pragma unroll
        for (int j = 0; j < 4; j++) { acc[i][j] = 0.0f; chk[i][j] = 0.0f; }

    float4 av = *(const float4*)(Aptr);
    float2 bv = *(const float2*)(Bptr);

    for (int k0 = 0; k0 < K; k0 += 8) {
        As[lcA + 0][lrA] = av.x; As[lcA + 1][lrA] = av.y;
        As[lcA + 2][lrA] = av.z; As[lcA + 3][lrA] = av.w;
        Bs[lcB + 0][lrB] = bv.x; Bs[lcB + 1][lrB] = bv.y;
        __syncthreads();

        if (k0 + 8 < K) {
            av = *(const float4*)(Aptr + k0 + 8);
            bv = *(const float2*)(Bptr + k0 + 8);
        }

        #pragma unroll
        for (int kk = 0; kk < 8; kk++) {
            float4 a0 = *(const float4*)&As[kk][ty * 4];
            float4 a1 = *(const float4*)&As[kk][64 + ty * 4];
            float4 b0 = *(const float4*)&Bs[kk][tx * 4];
            float ar[8] = {a0.x, a0.y, a0.z, a0.w, a1.x, a1.y, a1.z, a1.w};
            float br[4] = {b0.x, b0.y, b0.z, b0.w};
            #pragma unroll
            for (int i = 0; i < 8; i++)
                #pragma unroll
                for (int j = 0; j < 4; j++)
                    chk[i][j] = fmaf(ar[i], br[j], chk[i][j]);
        }
        // fold chunk into master every 32 k (4 k-tiles)
        if ((k0 & 24) == 24) {
            #pragma unroll
            for (int i = 0; i < 8; i++)
                #pragma unroll
                for (int j = 0; j < 4; j++) {
                    acc[i][j] = __fadd_rn(acc[i][j], chk[i][j]);
                    chk[i][j] = 0.0f;
                }
        }
        __syncthreads();
    }

    #pragma unroll
    for (int i = 0; i < 8; i++) {
        const int row = m0 + ((i < 4) ? (ty * 4 + i) : (64 + ty * 4 + i - 4));
        float4 r;
        float v0 = acc[i][0], v1 = acc[i][1], v2 = acc[i][2], v3 = acc[i][3];
        if (GELU) { v0 = gelu_f(v0); v1 = gelu_f(v1); v2 = gelu_f(v2); v3 = gelu_f(v3); }
        r.x = v0; r.y = v1; r.z = v2; r.w = v3;
        *(float4*)(C + (size_t)row * N + n0 + tx * 4) = r;
    }
}

// ---------------------------------------------------------------------------
// Per-row exact top-k (k=512 of 4096) via 4-pass radix select on monotone
// uint keys, then z <- mask * gelu(z) in place. Exact tie handling.
// ---------------------------------------------------------------------------
__global__ void __launch_bounds__(256) topk_mask_gelu(
    const float* __restrict__ scores, float* __restrict__ z)
{
    __shared__ unsigned int keys[DFF];
    __shared__ unsigned int hist[256];
    __shared__ unsigned char mask[DFF];

    const int row = blockIdx.x;
    const int tid = threadIdx.x;
    const float* srow = scores + (size_t)row * DFF;
    float* zrow = z + (size_t)row * DFF;

    for (int j = tid; j < DFF; j += 256) {
        unsigned int u = __float_as_uint(srow[j]);
        u = (u & 0x80000000u) ? ~u : (u | 0x80000000u);
        keys[j] = u;
    }

    unsigned int prefix = 0, pmask = 0;
    int remaining = TOPK;
    int lastcnt = 0;

    #pragma unroll
    for (int p = 0; p < 4; p++) {
        const int shift = 24 - 8 * p;
        __syncthreads();
        if (tid < 256) hist[tid] = 0;
        __syncthreads();
        for (int j = tid; j < DFF; j += 256) {
            unsigned int k = keys[j];
            if ((k & pmask) == prefix)
                atomicAdd(&hist[(k >> shift) & 255u], 1u);
        }
        __syncthreads();
        int cum = 0, digit = 0;
        for (int bbin = 255; bbin >= 0; bbin--) {
            int c = (int)hist[bbin];
            if (cum + c >= remaining) { digit = bbin; lastcnt = c; break; }
            cum += c;
        }
        remaining -= cum;
        prefix |= ((unsigned int)digit) << shift;
        pmask  |= 0xFFu << shift;
    }
    const unsigned int T = prefix;

    __syncthreads();
    for (int j = tid; j < DFF; j += 256)
        mask[j] = (keys[j] > T) ? (unsigned char)1 : (unsigned char)0;

    if (lastcnt == remaining) {
        for (int j = tid; j < DFF; j += 256)
            if (keys[j] == T) mask[j] = 1;
    } else {
        __syncthreads();
        if (tid == 0) {
            int need = remaining;
            for (int j = 0; j < DFF && need > 0; j++)
                if (keys[j] == T) { mask[j] = 1; need--; }
        }
    }
    __syncthreads();

    for (int j = tid; j < DFF; j += 256) {
        float v = mask[j] ? gelu_f(zrow[j]) : 0.0f;
        zrow[j] = v;
    }
}

// ---------------------------------------------------------------------------
// Launch
// Inputs: 0:x 1:W1 2:W2 3:W_router_1 4:W_router_2 5:ln_gamma 6:ln_beta 7:top_k
// ---------------------------------------------------------------------------
extern "C" void kernel_launch(void* const* d_in, const int* in_sizes, int n_in,
                              void* d_out, int out_size)
{
    const float* x    = (const float*)d_in[0];
    const float* W1   = (const float*)d_in[1];
    const float* W2   = (const float*)d_in[2];
    const float* Wr1  = (const float*)d_in[3];
    const float* Wr2  = (const float*)d_in[4];
    const float* gma  = (const float*)d_in[5];
    const float* bta  = (const float*)d_in[6];
    float* out = (float*)d_out;

    float *xn, *h, *sc, *z;
    cudaGetSymbolAddress((void**)&xn, g_xn);
    cudaGetSymbolAddress((void**)&h,  g_h);
    cudaGetSymbolAddress((void**)&sc, g_sc);
    cudaGetSymbolAddress((void**)&z,  g_z);

    // 1) xn = LN(x)
    ln_kernel<<<NROWS, 256>>>(x, gma, bta, xn);

    // 2) h = gelu(xn @ Wr1^T)   — accurate path
    gemm_bt_acc<true><<<dim3(DMODEL / 64, NROWS / 128), 256>>>(xn, Wr1, h, NROWS, DMODEL, DMODEL);

    // 3) scores = h @ Wr2^T     — accurate path
    gemm_bt_acc<false><<<dim3(DFF / 64, NROWS / 128), 256>>>(h, Wr2, sc, NROWS, DFF, DMODEL);

    // 4) z = x @ W1^T           — fast path
    gemm_bt<<<dim3(DFF / 128, NROWS / 128), 256>>>(x, W1, z, NROWS, DFF, DMODEL);

    // 5) top-512 per row of scores; z <- mask * gelu(z)
    topk_mask_gelu<<<NROWS, 256>>>(sc, z);

    // 6) out = z @ W2^T         — fast path
    gemm_bt<<<dim3(DMODEL / 128, NROWS / 128), 256>>>(z, W2, out, NROWS, DMODEL, DFF);
}

// round 5
// speedup vs baseline: 1.0065x; 1.0065x over previous
#include <cuda_runtime.h>
#include <stdint.h>
#include <cstdint>
#include <math.h>

// Problem shapes (fixed by setup_inputs)
#define NROWS 16384   // B*S
#define DMODEL 1024
#define DFF 4096
#define TOPK 512

// Scratch (device globals: no allocations allowed)
__device__ float g_xn[(size_t)NROWS * DMODEL];       // 64 MB
__device__ float g_h [(size_t)NROWS * DMODEL];       // 64 MB
__device__ float g_sc[(size_t)NROWS * DFF];          // 256 MB
__device__ float g_z [(size_t)NROWS * DFF];          // 256 MB

// ---------------------------------------------------------------------------
// XLA f32 erf polynomial, uncontracted mul/add
// ---------------------------------------------------------------------------
__device__ __forceinline__ float erf_xla(float xin) {
    float x = fminf(fmaxf(xin, -4.0f), 4.0f);
    float x2 = __fmul_rn(x, x);
    float p = -2.72614225801306e-10f;
    p = __fadd_rn(__fmul_rn(p, x2),  2.77068142495902e-08f);
    p = __fadd_rn(__fmul_rn(p, x2), -2.10102402082508e-06f);
    p = __fadd_rn(__fmul_rn(p, x2), -5.69250639462346e-05f);
    p = __fadd_rn(__fmul_rn(p, x2), -7.34990630326855e-04f);
    p = __fadd_rn(__fmul_rn(p, x2), -2.95459980854025e-03f);
    p = __fadd_rn(__fmul_rn(p, x2), -1.60960333262415e-02f);
    float q = -1.45660718464996e-05f;
    q = __fadd_rn(__fmul_rn(q, x2), -2.13374055278905e-04f);
    q = __fadd_rn(__fmul_rn(q, x2), -1.68282697438203e-03f);
    q = __fadd_rn(__fmul_rn(q, x2), -7.37332916720468e-03f);
    q = __fadd_rn(__fmul_rn(q, x2), -1.42647390514189e-02f);
    return __fdiv_rn(__fmul_rn(x, p), q);
}

// jax.nn.gelu(approximate=False): 0.5 * x * (1 + erf(x / sqrt(2)))
__device__ __forceinline__ float gelu_f(float v) {
    float t = __fdiv_rn(v, 1.41421356237309504880f);
    float e = erf_xla(t);
    return __fmul_rn(__fmul_rn(v, __fadd_rn(e, 1.0f)), 0.5f);
}

// ---------------------------------------------------------------------------
// LayerNorm: one block per row, fp64 statistics
// ---------------------------------------------------------------------------
__global__ void __launch_bounds__(256) ln_kernel(
    const float* __restrict__ x, const float* __restrict__ g,
    const float* __restrict__ b, float* __restrict__ o)
{
    __shared__ double red[8];
    __shared__ float s_mu, s_inv;
    const int row = blockIdx.x;
    const int tid = threadIdx.x;
    const float4* xr = (const float4*)(x + (size_t)row * DMODEL);
    float4* orow = (float4*)(o + (size_t)row * DMODEL);

    float4 v = xr[tid];

    double s = (double)v.x + (double)v.y + (double)v.z + (double)v.w;
    #pragma unroll
    for (int off = 16; off; off >>= 1) s += __shfl_down_sync(0xffffffffu, s, off);
    if ((tid & 31) == 0) red[tid >> 5] = s;
    __syncthreads();
    if (tid == 0) {
        double S = 0.0;
        #pragma unroll
        for (int w = 0; w < 8; w++) S += red[w];
        s_mu = (float)(S * (1.0 / DMODEL));
    }
    __syncthreads();
    const float mu = s_mu;
    __syncthreads();

    float dx0 = __fsub_rn(v.x, mu), dx1 = __fsub_rn(v.y, mu);
    float dx2 = __fsub_rn(v.z, mu), dx3 = __fsub_rn(v.w, mu);
    double ss = (double)__fmul_rn(dx0, dx0) + (double)__fmul_rn(dx1, dx1)
              + (double)__fmul_rn(dx2, dx2) + (double)__fmul_rn(dx3, dx3);
    #pragma unroll
    for (int off = 16; off; off >>= 1) ss += __shfl_down_sync(0xffffffffu, ss, off);
    if ((tid & 31) == 0) red[tid >> 5] = ss;
    __syncthreads();
    if (tid == 0) {
        double SS = 0.0;
        #pragma unroll
        for (int w = 0; w < 8; w++) SS += red[w];
        float var = (float)(SS * (1.0 / DMODEL));
        s_inv = (float)(1.0 / sqrt((double)__fadd_rn(var, 1e-5f)));
    }
    __syncthreads();
    const float inv = s_inv;
    const float4 gv = ((const float4*)g)[tid];
    const float4 bv = ((const float4*)b)[tid];
    float4 r;
    r.x = __fadd_rn(__fmul_rn(__fmul_rn(dx0, inv), gv.x), bv.x);
    r.y = __fadd_rn(__fmul_rn(__fmul_rn(dx1, inv), gv.y), bv.y);
    r.z = __fadd_rn(__fmul_rn(__fmul_rn(dx2, inv), gv.z), bv.z);
    r.w = __fadd_rn(__fmul_rn(__fmul_rn(dx3, inv), gv.w), bv.w);
    orow[tid] = r;
}

// ---------------------------------------------------------------------------
// Tensor-core 3xTF32 GEMM: C[M,N] = A[M,K] @ B[N,K]^T (value-accuracy path).
// mma.sync.m16n8k8 tf32, in-register hi/lo split (a=ah+al, b=bh+bl;
// acc += al*bh + ah*bl + ah*bh  -> residual ~2.4e-7, near-fp32 values).
// Block tile 128x64, 8 warps (warp tile 32x32), K-step 16, double-buffered.
// ---------------------------------------------------------------------------
__device__ __forceinline__ uint32_t cvt_tf32(float x) {
    uint32_t u; asm("cvt.rna.tf32.f32 %0, %1;" : "=r"(u) : "f"(x)); return u;
}
__device__ __forceinline__ void split_tf32(float x, uint32_t& hi, uint32_t& lo) {
    hi = cvt_tf32(x);
    lo = cvt_tf32(__fsub_rn(x, __uint_as_float(hi)));
}
__device__ __forceinline__ void mma8(float c[4], const uint32_t a[4], const uint32_t b[2]) {
    asm volatile("mma.sync.aligned.m16n8k8.row.col.f32.tf32.tf32.f32 "
        "{%0,%1,%2,%3}, {%4,%5,%6,%7}, {%8,%9}, {%0,%1,%2,%3};\n"
        : "+f"(c[0]), "+f"(c[1]), "+f"(c[2]), "+f"(c[3])
        : "r"(a[0]), "r"(a[1]), "r"(a[2]), "r"(a[3]), "r"(b[0]), "r"(b[1]));
}

__global__ void __launch_bounds__(256) gemm_bt_tf32(
    const float* __restrict__ A, const float* __restrict__ B,
    float* __restrict__ C, int M, int N, int K)
{
    __shared__ float As[2][128][20];   // 20-float row pitch: conflict-free frags
    __shared__ float Bs[2][64][20];

    const int tid  = threadIdx.x;
    const int m0   = blockIdx.y * 128;
    const int n0   = blockIdx.x * 64;
    const int wid  = tid >> 5;
    const int lane = tid & 31;
    const int gid  = lane >> 2;        // 0..7
    const int tig  = lane & 3;         // 0..3
    const int wm   = (wid & 3) * 32;   // warp m offset (4 warps over M)
    const int wn   = (wid >> 2) * 32;  // warp n offset (2 warps over N)

    // global->smem load assignments (K-step 16)
    const int arow = tid >> 1, akoff = (tid & 1) * 8;     // 8 floats/thread
    const int brow = tid >> 2, bkoff = (tid & 3) * 4;     // 4 floats/thread
    const float* Ag = A + (size_t)(m0 + arow) * K + akoff;
    const float* Bg = B + (size_t)(n0 + brow) * K + bkoff;

    float acc[2][4][4];
    #pragma unroll
    for (int mt = 0; mt < 2; mt++)
        #pragma unroll
        for (int nt = 0; nt < 4; nt++)
            #pragma unroll
            for (int r = 0; r < 4; r++) acc[mt][nt][r] = 0.0f;

    // prologue: stage 0
    float4 av0 = *(const float4*)(Ag);
    float4 av1 = *(const float4*)(Ag + 4);
    float4 bv  = *(const float4*)(Bg);
    {
        float* a = &As[0][arow][akoff];
        a[0]=av0.x; a[1]=av0.y; a[2]=av0.z; a[3]=av0.w;
        a[4]=av1.x; a[5]=av1.y; a[6]=av1.z; a[7]=av1.w;
        float* bp = &Bs[0][brow][bkoff];
        bp[0]=bv.x; bp[1]=bv.y; bp[2]=bv.z; bp[3]=bv.w;
    }

    int s = 0;
    for (int k0 = 0; k0 < K; k0 += 16) {
        __syncthreads();
        const bool nxt = (k0 + 16) < K;
        if (nxt) {
            av0 = *(const float4*)(Ag + k0 + 16);
            av1 = *(const float4*)(Ag + k0 + 20);
            bv  = *(const float4*)(Bg + k0 + 16);
        }

        #pragma unroll
        for (int kk = 0; kk < 16; kk += 8) {
            uint32_t ah[2][4], al[2][4];
            #pragma unroll
            for (int mt = 0; mt < 2; mt++) {
                const int rb = wm + mt * 16;
                float f0 = As[s][rb + gid    ][kk + tig];
                float f1 = As[s][rb + gid + 8][kk + tig];
                float f2 = As[s][rb + gid    ][kk + tig + 4];
                float f3 = As[s][rb + gid + 8][kk + tig + 4];
                split_tf32(f0, ah[mt][0], al[mt][0]);
                split_tf32(f1, ah[mt][1], al[mt][1]);
                split_tf32(f2, ah[mt][2], al[mt][2]);
                split_tf32(f3, ah[mt][3], al[mt][3]);
            }
            uint32_t bh[4][2], bl[4][2];
            #pragma unroll
            for (int nt = 0; nt < 4; nt++) {
                const int rb = wn + nt * 8;
                float f0 = Bs[s][rb + gid][kk + tig];
                float f1 = Bs[s][rb + gid][kk + tig + 4];
                split_tf32(f0, bh[nt][0], bl[nt][0]);
                split_tf32(f1, bh[nt][1], bl[nt][1]);
            }
            #pragma unroll
            for (int mt = 0; mt < 2; mt++)
                #pragma unroll
                for (int nt = 0; nt < 4; nt++) {
                    mma8(acc[mt][nt], al[mt], bh[nt]);
                    mma8(acc[mt][nt], ah[mt], bl[nt]);
                    mma8(acc[mt][nt], ah[mt], bh[nt]);
                }
        }

        if (nxt) {
            float* a = &As[s ^ 1][arow][akoff];
            a[0]=av0.x; a[1]=av0.y; a[2]=av0.z; a[3]=av0.w;
            a[4]=av1.x; a[5]=av1.y; a[6]=av1.z; a[7]=av1.w;
            float* bp = &Bs[s ^ 1][brow][bkoff];
            bp[0]=bv.x; bp[1]=bv.y; bp[2]=bv.z; bp[3]=bv.w;
        }
        s ^= 1;
    }

    // epilogue
    #pragma unroll
    for (int mt = 0; mt < 2; mt++)
        #pragma unroll
        for (int nt = 0; nt < 4; nt++) {
            const int r0 = m0 + wm + mt * 16 + gid;
            const int c0 = n0 + wn + nt * 8 + tig * 2;
            *(float2*)&C[(size_t)r0 * N + c0]       = make_float2(acc[mt][nt][0], acc[mt][nt][1]);
            *(float2*)&C[(size_t)(r0 + 8) * N + c0] = make_float2(acc[mt][nt][2], acc[mt][nt][3]);
        }
}

// ---------------------------------------------------------------------------
// ACCURATE path (router GEMMs): two-level chunked fp32 accumulation.
// (Controls top-k flip count — do not touch.)
// ---------------------------------------------------------------------------
template <bool GELU>
__global__ void __launch_bounds__(256) gemm_bt_acc(
    const float* __restrict__ A, const float* __restrict__ B,
    float* __restrict__ C, int M, int N, int K)
{
    __shared__ float As[8][128];
    __shared__ float Bs[8][64];

    const int m0 = blockIdx.y * 128;
    const int n0 = blockIdx.x * 64;
    const int tid = threadIdx.x;
    const int lrA = tid >> 1;
    const int lcA = (tid & 1) * 4;
    const int lrB = tid >> 2;
    const int lcB = (tid & 3) * 2;
    const int tx = tid & 15;
    const int ty = tid >> 4;

    const float* Aptr = A + (size_t)(m0 + lrA) * K + lcA;
    const float* Bptr = B + (size_t)(n0 + lrB) * K + lcB;

    float acc[8][4], chk[8][4];
    #pragma unroll
    for (int i = 0; i < 8; i++)
        #pragma unroll
        for (int j = 0; j < 4; j++) { acc[i][j] = 0.0f; chk[i][j] = 0.0f; }

    float4 av = *(const float4*)(Aptr);
    float2 bv = *(const float2*)(Bptr);

    for (int k0 = 0; k0 < K; k0 += 8) {
        As[lcA + 0][lrA] = av.x; As[lcA + 1][lrA] = av.y;
        As[lcA + 2][lrA] = av.z; As[lcA + 3][lrA] = av.w;
        Bs[lcB + 0][lrB] = bv.x; Bs[lcB + 1][lrB] = bv.y;
        __syncthreads();

        if (k0 + 8 < K) {
            av = *(const float4*)(Aptr + k0 + 8);
            bv = *(const float2*)(Bptr + k0 + 8);
        }

        #pragma unroll
        for (int kk = 0; kk < 8; kk++) {
            float4 a0 = *(const float4*)&As[kk][ty * 4];
            float4 a1 = *(const float4*)&As[kk][64 + ty * 4];
            float4 b0 = *(const float4*)&Bs[kk][tx * 4];
            float ar[8] = {a0.x, a0.y, a0.z, a0.w, a1.x, a1.y, a1.z, a1.w};
            float br[4] = {b0.x, b0.y, b0.z, b0.w};
            #pragma unroll
            for (int i = 0; i < 8; i++)
                #pragma unroll
                for (int j = 0; j < 4; j++)
                    chk[i][j] = fmaf(ar[i], br[j], chk[i][j]);
        }
        if ((k0 & 24) == 24) {
            #pragma unroll
            for (int i = 0; i < 8; i++)
                #pragma unroll
                for (int j = 0; j < 4; j++) {
                    acc[i][j] = __fadd_rn(acc[i][j], chk[i][j]);
                    chk[i][j] = 0.0f;
                }
        }
        __syncthreads();
    }

    #pragma unroll
    for (int i = 0; i < 8; i++) {
        const int row = m0 + ((i < 4) ? (ty * 4 + i) : (64 + ty * 4 + i - 4));
        float4 r;
        float v0 = acc[i][0], v1 = acc[i][1], v2 = acc[i][2], v3 = acc[i][3];
        if (GELU) { v0 = gelu_f(v0); v1 = gelu_f(v1); v2 = gelu_f(v2); v3 = gelu_f(v3); }
        r.x = v0; r.y = v1; r.z = v2; r.w = v3;
        *(float4*)(C + (size_t)row * N + n0 + tx * 4) = r;
    }
}

// ---------------------------------------------------------------------------
// Per-row exact top-k (radix select) + masked gelu of z (unchanged, passing)
// ---------------------------------------------------------------------------
__global__ void __launch_bounds__(256) topk_mask_gelu(
    const float* __restrict__ scores, float* __restrict__ z)
{
    __shared__ unsigned int keys[DFF];
    __shared__ unsigned int hist[256];
    __shared__ unsigned char mask[DFF];

    const int row = blockIdx.x;
    const int tid = threadIdx.x;
    const float* srow = scores + (size_t)row * DFF;
    float* zrow = z + (size_t)row * DFF;

    for (int j = tid; j < DFF; j += 256) {
        unsigned int u = __float_as_uint(srow[j]);
        u = (u & 0x80000000u) ? ~u : (u | 0x80000000u);
        keys[j] = u;
    }

    unsigned int prefix = 0, pmask = 0;
    int remaining = TOPK;
    int lastcnt = 0;

    #pragma unroll
    for (int p = 0; p < 4; p++) {
        const int shift = 24 - 8 * p;
        __syncthreads();
        if (tid < 256) hist[tid] = 0;
        __syncthreads();
        for (int j = tid; j < DFF; j += 256) {
            unsigned int k = keys[j];
            if ((k & pmask) == prefix)
                atomicAdd(&hist[(k >> shift) & 255u], 1u);
        }
        __syncthreads();
        int cum = 0, digit = 0;
        for (int bbin = 255; bbin >= 0; bbin--) {
            int c = (int)hist[bbin];
            if (cum + c >= remaining) { digit = bbin; lastcnt = c; break; }
            cum += c;
        }
        remaining -= cum;
        prefix |= ((unsigned int)digit) << shift;
        pmask  |= 0xFFu << shift;
    }
    const unsigned int T = prefix;

    __syncthreads();
    for (int j = tid; j < DFF; j += 256)
        mask[j] = (keys[j] > T) ? (unsigned char)1 : (unsigned char)0;

    if (lastcnt == remaining) {
        for (int j = tid; j < DFF; j += 256)
            if (keys[j] == T) mask[j] = 1;
    } else {
        __syncthreads();
        if (tid == 0) {
            int need = remaining;
            for (int j = 0; j < DFF && need > 0; j++)
                if (keys[j] == T) { mask[j] = 1; need--; }
        }
    }
    __syncthreads();

    for (int j = tid; j < DFF; j += 256) {
        float v = mask[j] ? gelu_f(zrow[j]) : 0.0f;
        zrow[j] = v;
    }
}

// ---------------------------------------------------------------------------
// Launch
// Inputs: 0:x 1:W1 2:W2 3:W_router_1 4:W_router_2 5:ln_gamma 6:ln_beta 7:top_k
// ---------------------------------------------------------------------------
extern "C" void kernel_launch(void* const* d_in, const int* in_sizes, int n_in,
                              void* d_out, int out_size)
{
    const float* x    = (const float*)d_in[0];
    const float* W1   = (const float*)d_in[1];
    const float* W2   = (const float*)d_in[2];
    const float* Wr1  = (const float*)d_in[3];
    const float* Wr2  = (const float*)d_in[4];
    const float* gma  = (const float*)d_in[5];
    const float* bta  = (const float*)d_in[6];
    float* out = (float*)d_out;

    float *xn, *h, *sc, *z;
    cudaGetSymbolAddress((void**)&xn, g_xn);
    cudaGetSymbolAddress((void**)&h,  g_h);
    cudaGetSymbolAddress((void**)&sc, g_sc);
    cudaGetSymbolAddress((void**)&z,  g_z);

    // 1) xn = LN(x)
    ln_kernel<<<NROWS, 256>>>(x, gma, bta, xn);

    // 2) h = gelu(xn @ Wr1^T)   — accurate fp32 path (selection-critical)
    gemm_bt_acc<true><<<dim3(DMODEL / 64, NROWS / 128), 256>>>(xn, Wr1, h, NROWS, DMODEL, DMODEL);

    // 3) scores = h @ Wr2^T     — accurate fp32 path (selection-critical)
    gemm_bt_acc<false><<<dim3(DFF / 64, NROWS / 128), 256>>>(h, Wr2, sc, NROWS, DFF, DMODEL);

    // 4) z = x @ W1^T           — tensor-core 3xTF32
    gemm_bt_tf32<<<dim3(DFF / 64, NROWS / 128), 256>>>(x, W1, z, NROWS, DFF, DMODEL);

    // 5) top-512 per row of scores; z <- mask * gelu(z)
    topk_mask_gelu<<<NROWS, 256>>>(sc, z);

    // 6) out = z @ W2^T         — tensor-core 3xTF32
    gemm_bt_tf32<<<dim3(DMODEL / 64, NROWS / 128), 256>>>(z, W2, out, NROWS, DMODEL, DFF);
}

// round 7
// speedup vs baseline: 1.0912x; 1.0841x over previous
#include <cuda_runtime.h>
#include <cuda_bf16.h>
#include <stdint.h>
#include <cstdint>
#include <math.h>

// Problem shapes (fixed by setup_inputs)
#define NROWS 16384   // B*S
#define DMODEL 1024
#define DFF 4096
#define TOPK 512

// Scratch (device globals: no allocations allowed)
__device__ float g_xn[(size_t)NROWS * DMODEL];
__device__ float g_h [(size_t)NROWS * DMODEL];
__device__ float g_sc[(size_t)NROWS * DFF];
__device__ float g_z [(size_t)NROWS * DFF];
// bf16 hi/lo splits for the tensor-core (mma.sync) path
__device__ __nv_bfloat16 g_xh [(size_t)NROWS * DMODEL];
__device__ __nv_bfloat16 g_xl [(size_t)NROWS * DMODEL];
__device__ __nv_bfloat16 g_w1h[(size_t)DFF * DMODEL];
__device__ __nv_bfloat16 g_w1l[(size_t)DFF * DMODEL];
__device__ __nv_bfloat16 g_w2h[(size_t)DMODEL * DFF];
__device__ __nv_bfloat16 g_w2l[(size_t)DMODEL * DFF];
__device__ __nv_bfloat16 g_zh [(size_t)NROWS * DFF];
__device__ __nv_bfloat16 g_zl [(size_t)NROWS * DFF];

// ---------------------------------------------------------------------------
// XLA f32 erf polynomial, uncontracted mul/add
// ---------------------------------------------------------------------------
__device__ __forceinline__ float erf_xla(float xin) {
    float x = fminf(fmaxf(xin, -4.0f), 4.0f);
    float x2 = __fmul_rn(x, x);
    float p = -2.72614225801306e-10f;
    p = __fadd_rn(__fmul_rn(p, x2),  2.77068142495902e-08f);
    p = __fadd_rn(__fmul_rn(p, x2), -2.10102402082508e-06f);
    p = __fadd_rn(__fmul_rn(p, x2), -5.69250639462346e-05f);
    p = __fadd_rn(__fmul_rn(p, x2), -7.34990630326855e-04f);
    p = __fadd_rn(__fmul_rn(p, x2), -2.95459980854025e-03f);
    p = __fadd_rn(__fmul_rn(p, x2), -1.60960333262415e-02f);
    float q = -1.45660718464996e-05f;
    q = __fadd_rn(__fmul_rn(q, x2), -2.13374055278905e-04f);
    q = __fadd_rn(__fmul_rn(q, x2), -1.68282697438203e-03f);
    q = __fadd_rn(__fmul_rn(q, x2), -7.37332916720468e-03f);
    q = __fadd_rn(__fmul_rn(q, x2), -1.42647390514189e-02f);
    return __fdiv_rn(__fmul_rn(x, p), q);
}

__device__ __forceinline__ float gelu_f(float v) {
    float t = __fdiv_rn(v, 1.41421356237309504880f);
    float e = erf_xla(t);
    return __fmul_rn(__fmul_rn(v, __fadd_rn(e, 1.0f)), 0.5f);
}

// ---------------------------------------------------------------------------
// LayerNorm: one block per row, fp64 statistics (unchanged, passing)
// ---------------------------------------------------------------------------
__global__ void __launch_bounds__(256) ln_kernel(
    const float* __restrict__ x, const float* __restrict__ g,
    const float* __restrict__ b, float* __restrict__ o)
{
    __shared__ double red[8];
    __shared__ float s_mu, s_inv;
    const int row = blockIdx.x;
    const int tid = threadIdx.x;
    const float4* xr = (const float4*)(x + (size_t)row * DMODEL);
    float4* orow = (float4*)(o + (size_t)row * DMODEL);

    float4 v = xr[tid];

    double s = (double)v.x + (double)v.y + (double)v.z + (double)v.w;
    #pragma unroll
    for (int off = 16; off; off >>= 1) s += __shfl_down_sync(0xffffffffu, s, off);
    if ((tid & 31) == 0) red[tid >> 5] = s;
    __syncthreads();
    if (tid == 0) {
        double S = 0.0;
        #pragma unroll
        for (int w = 0; w < 8; w++) S += red[w];
        s_mu = (float)(S * (1.0 / DMODEL));
    }
    __syncthreads();
    const float mu = s_mu;
    __syncthreads();

    float dx0 = __fsub_rn(v.x, mu), dx1 = __fsub_rn(v.y, mu);
    float dx2 = __fsub_rn(v.z, mu), dx3 = __fsub_rn(v.w, mu);
    double ss = (double)__fmul_rn(dx0, dx0) + (double)__fmul_rn(dx1, dx1)
              + (double)__fmul_rn(dx2, dx2) + (double)__fmul_rn(dx3, dx3);
    #pragma unroll
    for (int off = 16; off; off >>= 1) ss += __shfl_down_sync(0xffffffffu, ss, off);
    if ((tid & 31) == 0) red[tid >> 5] = ss;
    __syncthreads();
    if (tid == 0) {
        double SS = 0.0;
        #pragma unroll
        for (int w = 0; w < 8; w++) SS += red[w];
        float var = (float)(SS * (1.0 / DMODEL));
        s_inv = (float)(1.0 / sqrt((double)__fadd_rn(var, 1e-5f)));
    }
    __syncthreads();
    const float inv = s_inv;
    const float4 gv = ((const float4*)g)[tid];
    const float4 bv = ((const float4*)b)[tid];
    float4 r;
    r.x = __fadd_rn(__fmul_rn(__fmul_rn(dx0, inv), gv.x), bv.x);
    r.y = __fadd_rn(__fmul_rn(__fmul_rn(dx1, inv), gv.y), bv.y);
    r.z = __fadd_rn(__fmul_rn(__fmul_rn(dx2, inv), gv.z), bv.z);
    r.w = __fadd_rn(__fmul_rn(__fmul_rn(dx3, inv), gv.w), bv.w);
    orow[tid] = r;
}

// ---------------------------------------------------------------------------
// Elementwise fp32 -> bf16 hi/lo split (pre-pass for tensor-core GEMMs)
// ---------------------------------------------------------------------------
union bfu { __nv_bfloat162 b; unsigned int u; };

__device__ __forceinline__ void split2(float a, float b, unsigned int& hi, unsigned int& lo) {
    __nv_bfloat16 h0 = __float2bfloat16_rn(a);
    __nv_bfloat16 h1 = __float2bfloat16_rn(b);
    __nv_bfloat16 l0 = __float2bfloat16_rn(__fsub_rn(a, __bfloat162float(h0)));
    __nv_bfloat16 l1 = __float2bfloat16_rn(__fsub_rn(b, __bfloat162float(h1)));
    bfu H; H.b = __nv_bfloat162(h0, h1); hi = H.u;
    bfu L; L.b = __nv_bfloat162(l0, l1); lo = L.u;
}

__global__ void __launch_bounds__(256) split_bf16_kernel(
    const float* __restrict__ src, __nv_bfloat16* __restrict__ hi,
    __nv_bfloat16* __restrict__ lo, size_t n4)
{
    size_t i = (size_t)blockIdx.x * 256 + threadIdx.x;
    size_t stride = (size_t)gridDim.x * 256;
    for (; i < n4; i += stride) {
        float4 v = ((const float4*)src)[i];
        uint2 H, L;
        split2(v.x, v.y, H.x, L.x);
        split2(v.z, v.w, H.y, L.y);
        ((uint2*)hi)[i] = H;
        ((uint2*)lo)[i] = L;
    }
}

// ---------------------------------------------------------------------------
// Tensor-core 3-term bf16 GEMM: C[M,N] = A[M,K] @ B[N,K]^T, fp32 accum.
// mma.sync.m16n8k16 bf16, pre-split hi/lo operands (no cvt in loop).
// acc += Ah*Bh + Ah*Bl + Al*Bh  -> residual ~1.5e-5 relative (value path).
// Block tile 128x64, 8 warps (warp tile 32x32), K-step 16, double-buffered.
// ---------------------------------------------------------------------------
__device__ __forceinline__ void mma16_bf16(float c[4], const unsigned int a[4],
                                           const unsigned int b[2]) {
    asm volatile("mma.sync.aligned.m16n8k16.row.col.f32.bf16.bf16.f32 "
        "{%0,%1,%2,%3}, {%4,%5,%6,%7}, {%8,%9}, {%0,%1,%2,%3};\n"
        : "+f"(c[0]), "+f"(c[1]), "+f"(c[2]), "+f"(c[3])
        : "r"(a[0]), "r"(a[1]), "r"(a[2]), "r"(a[3]), "r"(b[0]), "r"(b[1]));
}

__global__ void __launch_bounds__(256) gemm_bt_bf16(
    const __nv_bfloat16* __restrict__ Ahg, const __nv_bfloat16* __restrict__ Alg,
    const __nv_bfloat16* __restrict__ Bhg, const __nv_bfloat16* __restrict__ Blg,
    float* __restrict__ C, int M, int N, int K)
{
    // 24-element row pitch (48B): conflict-free 4B fragment LDS
    __shared__ __nv_bfloat16 Ah[2][128][24];
    __shared__ __nv_bfloat16 Al[2][128][24];
    __shared__ __nv_bfloat16 Bh[2][64][24];
    __shared__ __nv_bfloat16 Bl[2][64][24];

    const int tid  = threadIdx.x;
    const int m0   = blockIdx.y * 128;
    const int n0   = blockIdx.x * 64;
    const int wid  = tid >> 5;
    const int lane = tid & 31;
    const int gid  = lane >> 2;        // 0..7
    const int tig  = lane & 3;         // 0..3
    const int wm   = (wid & 3) * 32;   // 4 warps over M
    const int wn   = (wid >> 2) * 32;  // 2 warps over N

    // global->smem assignments (K-step 16)
    const int arow = tid >> 1, ak = (tid & 1) * 8;   // 8 bf16 (uint4) per thread
    const int brow = tid >> 2, bk = (tid & 3) * 4;   // 4 bf16 (uint2) per thread
    const size_t aoff = (size_t)(m0 + arow) * K + ak;
    const size_t boff = (size_t)(n0 + brow) * K + bk;

    float acc[2][4][4];
    #pragma unroll
    for (int mt = 0; mt < 2; mt++)
        #pragma unroll
        for (int nt = 0; nt < 4; nt++)
            #pragma unroll
            for (int r = 0; r < 4; r++) acc[mt][nt][r] = 0.0f;

    // prologue: stage 0
    uint4 pah = *(const uint4*)(Ahg + aoff);
    uint4 pal = *(const uint4*)(Alg + aoff);
    uint2 pbh = *(const uint2*)(Bhg + boff);
    uint2 pbl = *(const uint2*)(Blg + boff);
    *(uint4*)&Ah[0][arow][ak] = pah;
    *(uint4*)&Al[0][arow][ak] = pal;
    *(uint2*)&Bh[0][brow][bk] = pbh;
    *(uint2*)&Bl[0][brow][bk] = pbl;

    int s = 0;
    for (int k0 = 0; k0 < K; k0 += 16) {
        __syncthreads();
        const bool nxt = (k0 + 16) < K;
        if (nxt) {
            pah = *(const uint4*)(Ahg + aoff + k0 + 16);
            pal = *(const uint4*)(Alg + aoff + k0 + 16);
            pbh = *(const uint2*)(Bhg + boff + k0 + 16);
            pbl = *(const uint2*)(Blg + boff + k0 + 16);
        }

        // A fragments (hi & lo) for 2 m-tiles
        unsigned int afh[2][4], afl[2][4];
        #pragma unroll
        for (int mt = 0; mt < 2; mt++) {
            const int rb = wm + mt * 16;
            afh[mt][0] = *(const unsigned int*)&Ah[s][rb + gid    ][tig * 2];
            afh[mt][1] = *(const unsigned int*)&Ah[s][rb + gid + 8][tig * 2];
            afh[mt][2] = *(const unsigned int*)&Ah[s][rb + gid    ][tig * 2 + 8];
            afh[mt][3] = *(const unsigned int*)&Ah[s][rb + gid + 8][tig * 2 + 8];
            afl[mt][0] = *(const unsigned int*)&Al[s][rb + gid    ][tig * 2];
            afl[mt][1] = *(const unsigned int*)&Al[s][rb + gid + 8][tig * 2];
            afl[mt][2] = *(const unsigned int*)&Al[s][rb + gid    ][tig * 2 + 8];
            afl[mt][3] = *(const unsigned int*)&Al[s][rb + gid + 8][tig * 2 + 8];
        }
        // B fragments (hi & lo) for 4 n-tiles
        unsigned int bfh[4][2], bfl[4][2];
        #pragma unroll
        for (int nt = 0; nt < 4; nt++) {
            const int rb = wn + nt * 8 + gid;
            bfh[nt][0] = *(const unsigned int*)&Bh[s][rb][tig * 2];
            bfh[nt][1] = *(const unsigned int*)&Bh[s][rb][tig * 2 + 8];
            bfl[nt][0] = *(const unsigned int*)&Bl[s][rb][tig * 2];
            bfl[nt][1] = *(const unsigned int*)&Bl[s][rb][tig * 2 + 8];
        }
        #pragma unroll
        for (int mt = 0; mt < 2; mt++)
            #pragma unroll
            for (int nt = 0; nt < 4; nt++) {
                mma16_bf16(acc[mt][nt], afh[mt], bfh[nt]);
                mma16_bf16(acc[mt][nt], afh[mt], bfl[nt]);
                mma16_bf16(acc[mt][nt], afl[mt], bfh[nt]);
            }

        if (nxt) {
            *(uint4*)&Ah[s ^ 1][arow][ak] = pah;
            *(uint4*)&Al[s ^ 1][arow][ak] = pal;
            *(uint2*)&Bh[s ^ 1][brow][bk] = pbh;
            *(uint2*)&Bl[s ^ 1][brow][bk] = pbl;
        }
        s ^= 1;
    }

    // epilogue
    #pragma unroll
    for (int mt = 0; mt < 2; mt++)
        #pragma unroll
        for (int nt = 0; nt < 4; nt++) {
            const int r0 = m0 + wm + mt * 16 + gid;
            const int c0 = n0 + wn + nt * 8 + tig * 2;
            *(float2*)&C[(size_t)r0 * N + c0]       = make_float2(acc[mt][nt][0], acc[mt][nt][1]);
            *(float2*)&C[(size_t)(r0 + 8) * N + c0] = make_float2(acc[mt][nt][2], acc[mt][nt][3]);
        }
}

// ---------------------------------------------------------------------------
// ACCURATE path (router GEMMs): two-level chunked fp32 accumulation.
// (Controls top-k flip count — unchanged, passing.)
// ---------------------------------------------------------------------------
template <bool GELU>
__global__ void __launch_bounds__(256) gemm_bt_acc(
    const float* __restrict__ A, const float* __restrict__ B,
    float* __restrict__ C, int M, int N, int K)
{
    __shared__ float As[8][128];
    __shared__ float Bs[8][64];

    const int m0 = blockIdx.y * 128;
    const int n0 = blockIdx.x * 64;
    const int tid = threadIdx.x;
    const int lrA = tid >> 1;
    const int lcA = (tid & 1) * 4;
    const int lrB = tid >> 2;
    const int lcB = (tid & 3) * 2;
    const int tx = tid & 15;
    const int ty = tid >> 4;

    const float* Aptr = A + (size_t)(m0 + lrA) * K + lcA;
    const float* Bptr = B + (size_t)(n0 + lrB) * K + lcB;

    float acc[8][4], chk[8][4];
    #pragma unroll
    for (int i = 0; i < 8; i++)
        #pragma unroll
        for (int j = 0; j < 4; j++) { acc[i][j] = 0.0f; chk[i][j] = 0.0f; }

    float4 av = *(const float4*)(Aptr);
    float2 bv = *(const float2*)(Bptr);

    for (int k0 = 0; k0 < K; k0 += 8) {
        As[lcA + 0][lrA] = av.x; As[lcA + 1][lrA] = av.y;
        As[lcA + 2][lrA] = av.z; As[lcA + 3][lrA] = av.w;
        Bs[lcB + 0][lrB] = bv.x; Bs[lcB + 1][lrB] = bv.y;
        __syncthreads();

        if (k0 + 8 < K) {
            av = *(const float4*)(Aptr + k0 + 8);
            bv = *(const float2*)(Bptr + k0 + 8);
        }

        #pragma unroll
        for (int kk = 0; kk < 8; kk++) {
            float4 a0 = *(const float4*)&As[kk][ty * 4];
            float4 a1 = *(const float4*)&As[kk][64 + ty * 4];
            float4 b0 = *(const float4*)&Bs[kk][tx * 4];
            float ar[8] = {a0.x, a0.y, a0.z, a0.w, a1.x, a1.y, a1.z, a1.w};
            float br[4] = {b0.x, b0.y, b0.z, b0.w};
            #pragma unroll
            for (int i = 0; i < 8; i++)
                #pragma unroll
                for (int j = 0; j < 4; j++)
                    chk[i][j] = fmaf(ar[i], br[j], chk[i][j]);
        }
        if ((k0 & 24) == 24) {
            #pragma unroll
            for (int i = 0; i < 8; i++)
                #pragma unroll
                for (int j = 0; j < 4; j++) {
                    acc[i][j] = __fadd_rn(acc[i][j], chk[i][j]);
                    chk[i][j] = 0.0f;
                }
        }
        __syncthreads();
    }

    #pragma unroll
    for (int i = 0; i < 8; i++) {
        const int row = m0 + ((i < 4) ? (ty * 4 + i) : (64 + ty * 4 + i - 4));
        float4 r;
        float v0 = acc[i][0], v1 = acc[i][1], v2 = acc[i][2], v3 = acc[i][3];
        if (GELU) { v0 = gelu_f(v0); v1 = gelu_f(v1); v2 = gelu_f(v2); v3 = gelu_f(v3); }
        r.x = v0; r.y = v1; r.z = v2; r.w = v3;
        *(float4*)(C + (size_t)row * N + n0 + tx * 4) = r;
    }
}

// ---------------------------------------------------------------------------
// Per-row exact top-k (radix select), then write gelu(z)*mask split into
// bf16 hi/lo (feeds the bf16 out-GEMM). Selection logic unchanged.
// ---------------------------------------------------------------------------
__global__ void __launch_bounds__(256) topk_mask_gelu_split(
    const float* __restrict__ scores, const float* __restrict__ z,
    __nv_bfloat16* __restrict__ zh, __nv_bfloat16* __restrict__ zl)
{
    __shared__ unsigned int keys[DFF];
    __shared__ unsigned int hist[256];
    __shared__ unsigned char mask[DFF];

    const int row = blockIdx.x;
    const int tid = threadIdx.x;
    const float* srow = scores + (size_t)row * DFF;
    const float* zrow = z + (size_t)row * DFF;

    for (int j = tid; j < DFF; j += 256) {
        unsigned int u = __float_as_uint(srow[j]);
        u = (u & 0x80000000u) ? ~u : (u | 0x80000000u);
        keys[j] = u;
    }

    unsigned int prefix = 0, pmask = 0;
    int remaining = TOPK;
    int lastcnt = 0;

    #pragma unroll
    for (int p = 0; p < 4; p++) {
        const int shift = 24 - 8 * p;
        __syncthreads();
        if (tid < 256) hist[tid] = 0;
        __syncthreads();
        for (int j = tid; j < DFF; j += 256) {
            unsigned int k = keys[j];
            if ((k & pmask) == prefix)
                atomicAdd(&hist[(k >> shift) & 255u], 1u);
        }
        __syncthreads();
        int cum = 0, digit = 0;
        for (int bbin = 255; bbin >= 0; bbin--) {
            int c = (int)hist[bbin];
            if (cum + c >= remaining) { digit = bbin; lastcnt = c; break; }
            cum += c;
        }
        remaining -= cum;
        prefix |= ((unsigned int)digit) << shift;
        pmask  |= 0xFFu << shift;
    }
    const unsigned int T = prefix;

    __syncthreads();
    for (int j = tid; j < DFF; j += 256)
        mask[j] = (keys[j] > T) ? (unsigned char)1 : (unsigned char)0;

    if (lastcnt == remaining) {
        for (int j = tid; j < DFF; j += 256)
            if (keys[j] == T) mask[j] = 1;
    } else {
        __syncthreads();
        if (tid == 0) {
            int need = remaining;
            for (int j = 0; j < DFF && need > 0; j++)
                if (keys[j] == T) { mask[j] = 1; need--; }
        }
    }
    __syncthreads();

    for (int j = tid * 2; j < DFF; j += 512) {
        float v0 = mask[j]     ? gelu_f(zrow[j])     : 0.0f;
        float v1 = mask[j + 1] ? gelu_f(zrow[j + 1]) : 0.0f;
        unsigned int H, L;
        split2(v0, v1, H, L);
        *(unsigned int*)(zh + (size_t)row * DFF + j) = H;
        *(unsigned int*)(zl + (size_t)row * DFF + j) = L;
    }
}

// ---------------------------------------------------------------------------
// Launch
// Inputs: 0:x 1:W1 2:W2 3:W_router_1 4:W_router_2 5:ln_gamma 6:ln_beta 7:top_k
// ---------------------------------------------------------------------------
extern "C" void kernel_launch(void* const* d_in, const int* in_sizes, int n_in,
                              void* d_out, int out_size)
{
    const float* x    = (const float*)d_in[0];
    const float* W1   = (const float*)d_in[1];
    const float* W2   = (const float*)d_in[2];
    const float* Wr1  = (const float*)d_in[3];
    const float* Wr2  = (const float*)d_in[4];
    const float* gma  = (const float*)d_in[5];
    const float* bta  = (const float*)d_in[6];
    float* out = (float*)d_out;

    float *xn, *h, *sc, *z;
    __nv_bfloat16 *xh, *xl, *w1h, *w1l, *w2h, *w2l, *zh, *zl;
    cudaGetSymbolAddress((void**)&xn, g_xn);
    cudaGetSymbolAddress((void**)&h,  g_h);
    cudaGetSymbolAddress((void**)&sc, g_sc);
    cudaGetSymbolAddress((void**)&z,  g_z);
    cudaGetSymbolAddress((void**)&xh, g_xh);
    cudaGetSymbolAddress((void**)&xl, g_xl);
    cudaGetSymbolAddress((void**)&w1h, g_w1h);
    cudaGetSymbolAddress((void**)&w1l, g_w1l);
    cudaGetSymbolAddress((void**)&w2h, g_w2h);
    cudaGetSymbolAddress((void**)&w2l, g_w2l);
    cudaGetSymbolAddress((void**)&zh, g_zh);
    cudaGetSymbolAddress((void**)&zl, g_zl);

    // 1) xn = LN(x)
    ln_kernel<<<NROWS, 256>>>(x, gma, bta, xn);

    // 1b) bf16 hi/lo splits (x, W1, W2)
    split_bf16_kernel<<<2048, 256>>>(x,  xh,  xl,  (size_t)NROWS * DMODEL / 4);
    split_bf16_kernel<<<1024, 256>>>(W1, w1h, w1l, (size_t)DFF * DMODEL / 4);
    split_bf16_kernel<<<1024, 256>>>(W2, w2h, w2l, (size_t)DMODEL * DFF / 4);

    // 2) h = gelu(xn @ Wr1^T)   — accurate fp32 path (selection-critical)
    gemm_bt_acc<true><<<dim3(DMODEL / 64, NROWS / 128), 256>>>(xn, Wr1, h, NROWS, DMODEL, DMODEL);

    // 3) scores = h @ Wr2^T     — accurate fp32 path (selection-critical)
    gemm_bt_acc<false><<<dim3(DFF / 64, NROWS / 128), 256>>>(h, Wr2, sc, NROWS, DFF, DMODEL);

    // 4) z = x @ W1^T           — bf16 3-term tensor-core path
    gemm_bt_bf16<<<dim3(DFF / 64, NROWS / 128), 256>>>(
        xh, xl, w1h, w1l, z, NROWS, DFF, DMODEL);

    // 5) top-512 per row; zh/zl = split(mask * gelu(z))
    topk_mask_gelu_split<<<NROWS, 256>>>(sc, z, zh, zl);

    // 6) out = z @ W2^T         — bf16 3-term tensor-core path
    gemm_bt_bf16<<<dim3(DMODEL / 64, NROWS / 128), 256>>>(
        zh, zl, w2h, w2l, out, NROWS, DMODEL, DFF);
}

// round 8
// speedup vs baseline: 1.2648x; 1.1592x over previous
#include <cuda_runtime.h>
#include <cuda_bf16.h>
#include <stdint.h>
#include <cstdint>
#include <math.h>

// Problem shapes (fixed by setup_inputs)
#define NROWS 16384   // B*S
#define DMODEL 1024
#define DFF 4096
#define TOPK 512

// Scratch (device globals: no allocations allowed)
__device__ float g_xn[(size_t)NROWS * DMODEL];
__device__ float g_h [(size_t)NROWS * DMODEL];
__device__ float g_sc[(size_t)NROWS * DFF];
__device__ float g_z [(size_t)NROWS * DFF];
// bf16 hi/lo splits for the tensor-core (mma.sync) path
__device__ __nv_bfloat16 g_xh [(size_t)NROWS * DMODEL];
__device__ __nv_bfloat16 g_xl [(size_t)NROWS * DMODEL];
__device__ __nv_bfloat16 g_w1h[(size_t)DFF * DMODEL];
__device__ __nv_bfloat16 g_w1l[(size_t)DFF * DMODEL];
__device__ __nv_bfloat16 g_w2h[(size_t)DMODEL * DFF];
__device__ __nv_bfloat16 g_w2l[(size_t)DMODEL * DFF];
__device__ __nv_bfloat16 g_zh [(size_t)NROWS * DFF];
__device__ __nv_bfloat16 g_zl [(size_t)NROWS * DFF];

// ---------------------------------------------------------------------------
// XLA f32 erf polynomial, uncontracted mul/add
// ---------------------------------------------------------------------------
__device__ __forceinline__ float erf_xla(float xin) {
    float x = fminf(fmaxf(xin, -4.0f), 4.0f);
    float x2 = __fmul_rn(x, x);
    float p = -2.72614225801306e-10f;
    p = __fadd_rn(__fmul_rn(p, x2),  2.77068142495902e-08f);
    p = __fadd_rn(__fmul_rn(p, x2), -2.10102402082508e-06f);
    p = __fadd_rn(__fmul_rn(p, x2), -5.69250639462346e-05f);
    p = __fadd_rn(__fmul_rn(p, x2), -7.34990630326855e-04f);
    p = __fadd_rn(__fmul_rn(p, x2), -2.95459980854025e-03f);
    p = __fadd_rn(__fmul_rn(p, x2), -1.60960333262415e-02f);
    float q = -1.45660718464996e-05f;
    q = __fadd_rn(__fmul_rn(q, x2), -2.13374055278905e-04f);
    q = __fadd_rn(__fmul_rn(q, x2), -1.68282697438203e-03f);
    q = __fadd_rn(__fmul_rn(q, x2), -7.37332916720468e-03f);
    q = __fadd_rn(__fmul_rn(q, x2), -1.42647390514189e-02f);
    return __fdiv_rn(__fmul_rn(x, p), q);
}

__device__ __forceinline__ float gelu_f(float v) {
    float t = __fdiv_rn(v, 1.41421356237309504880f);
    float e = erf_xla(t);
    return __fmul_rn(__fmul_rn(v, __fadd_rn(e, 1.0f)), 0.5f);
}

// ---------------------------------------------------------------------------
// LayerNorm: one block per row, fp64 statistics (unchanged, passing)
// ---------------------------------------------------------------------------
__global__ void __launch_bounds__(256) ln_kernel(
    const float* __restrict__ x, const float* __restrict__ g,
    const float* __restrict__ b, float* __restrict__ o)
{
    __shared__ double red[8];
    __shared__ float s_mu, s_inv;
    const int row = blockIdx.x;
    const int tid = threadIdx.x;
    const float4* xr = (const float4*)(x + (size_t)row * DMODEL);
    float4* orow = (float4*)(o + (size_t)row * DMODEL);

    float4 v = xr[tid];

    double s = (double)v.x + (double)v.y + (double)v.z + (double)v.w;
    #pragma unroll
    for (int off = 16; off; off >>= 1) s += __shfl_down_sync(0xffffffffu, s, off);
    if ((tid & 31) == 0) red[tid >> 5] = s;
    __syncthreads();
    if (tid == 0) {
        double S = 0.0;
        #pragma unroll
        for (int w = 0; w < 8; w++) S += red[w];
        s_mu = (float)(S * (1.0 / DMODEL));
    }
    __syncthreads();
    const float mu = s_mu;
    __syncthreads();

    float dx0 = __fsub_rn(v.x, mu), dx1 = __fsub_rn(v.y, mu);
    float dx2 = __fsub_rn(v.z, mu), dx3 = __fsub_rn(v.w, mu);
    double ss = (double)__fmul_rn(dx0, dx0) + (double)__fmul_rn(dx1, dx1)
              + (double)__fmul_rn(dx2, dx2) + (double)__fmul_rn(dx3, dx3);
    #pragma unroll
    for (int off = 16; off; off >>= 1) ss += __shfl_down_sync(0xffffffffu, ss, off);
    if ((tid & 31) == 0) red[tid >> 5] = ss;
    __syncthreads();
    if (tid == 0) {
        double SS = 0.0;
        #pragma unroll
        for (int w = 0; w < 8; w++) SS += red[w];
        float var = (float)(SS * (1.0 / DMODEL));
        s_inv = (float)(1.0 / sqrt((double)__fadd_rn(var, 1e-5f)));
    }
    __syncthreads();
    const float inv = s_inv;
    const float4 gv = ((const float4*)g)[tid];
    const float4 bv = ((const float4*)b)[tid];
    float4 r;
    r.x = __fadd_rn(__fmul_rn(__fmul_rn(dx0, inv), gv.x), bv.x);
    r.y = __fadd_rn(__fmul_rn(__fmul_rn(dx1, inv), gv.y), bv.y);
    r.z = __fadd_rn(__fmul_rn(__fmul_rn(dx2, inv), gv.z), bv.z);
    r.w = __fadd_rn(__fmul_rn(__fmul_rn(dx3, inv), gv.w), bv.w);
    orow[tid] = r;
}

// ---------------------------------------------------------------------------
// Elementwise fp32 -> bf16 hi/lo split
// ---------------------------------------------------------------------------
union bfu { __nv_bfloat162 b; unsigned int u; };

__device__ __forceinline__ void split2(float a, float b, unsigned int& hi, unsigned int& lo) {
    __nv_bfloat16 h0 = __float2bfloat16_rn(a);
    __nv_bfloat16 h1 = __float2bfloat16_rn(b);
    __nv_bfloat16 l0 = __float2bfloat16_rn(__fsub_rn(a, __bfloat162float(h0)));
    __nv_bfloat16 l1 = __float2bfloat16_rn(__fsub_rn(b, __bfloat162float(h1)));
    bfu H; H.b = __nv_bfloat162(h0, h1); hi = H.u;
    bfu L; L.b = __nv_bfloat162(l0, l1); lo = L.u;
}

__global__ void __launch_bounds__(256) split_bf16_kernel(
    const float* __restrict__ src, __nv_bfloat16* __restrict__ hi,
    __nv_bfloat16* __restrict__ lo, size_t n4)
{
    size_t i = (size_t)blockIdx.x * 256 + threadIdx.x;
    size_t stride = (size_t)gridDim.x * 256;
    for (; i < n4; i += stride) {
        float4 v = ((const float4*)src)[i];
        uint2 H, L;
        split2(v.x, v.y, H.x, L.x);
        split2(v.z, v.w, H.y, L.y);
        ((uint2*)hi)[i] = H;
        ((uint2*)lo)[i] = L;
    }
}

// ---------------------------------------------------------------------------
// mma / ldmatrix / cp.async primitives (family-portable PTX only)
// ---------------------------------------------------------------------------
__device__ __forceinline__ void mma16_bf16(float c[4], const unsigned int a[4],
                                           const unsigned int b[2]) {
    asm volatile("mma.sync.aligned.m16n8k16.row.col.f32.bf16.bf16.f32 "
        "{%0,%1,%2,%3}, {%4,%5,%6,%7}, {%8,%9}, {%0,%1,%2,%3};\n"
        : "+f"(c[0]), "+f"(c[1]), "+f"(c[2]), "+f"(c[3])
        : "r"(a[0]), "r"(a[1]), "r"(a[2]), "r"(a[3]), "r"(b[0]), "r"(b[1]));
}
__device__ __forceinline__ void ldsm4(unsigned int& r0, unsigned int& r1,
                                      unsigned int& r2, unsigned int& r3,
                                      const void* p) {
    unsigned int a = (unsigned int)__cvta_generic_to_shared(p);
    asm volatile("ldmatrix.sync.aligned.m8n8.x4.shared.b16 {%0,%1,%2,%3}, [%4];"
                 : "=r"(r0), "=r"(r1), "=r"(r2), "=r"(r3) : "r"(a));
}
__device__ __forceinline__ void cpa16(void* s, const void* g) {
    unsigned int a = (unsigned int)__cvta_generic_to_shared(s);
    asm volatile("cp.async.cg.shared.global [%0], [%1], 16;\n"
                 :: "r"(a), "l"(g) : "memory");
}
__device__ __forceinline__ void cpa_commit() {
    asm volatile("cp.async.commit_group;\n" ::: "memory");
}
template <int N>
__device__ __forceinline__ void cpa_wait() {
    asm volatile("cp.async.wait_group %0;\n" :: "n"(N) : "memory");
}

// ---------------------------------------------------------------------------
// bf16 3-term GEMM body v2: ldmatrix + cp.async 3-stage pipeline.
// C[M,N] = A@B^T (fp32 accum). Block 128x64, 8 warps (32x32 warp tile).
// Dynamic smem layout per stage (stride 18432B):
//   AH @0 (128 rows x 48B pitch), AL @6144, BH @12288 (64 rows), BL @15360.
// ---------------------------------------------------------------------------
#define STG_STRIDE 18432
#define TC_DYNSMEM (3 * STG_STRIDE)

__device__ __forceinline__ void issue_chunk(
    char* sm, int st, int k0,
    const __nv_bfloat16* Ag0, const __nv_bfloat16* Ag1, const __nv_bfloat16* Bg,
    int arow, int akb, int brow, int bkb, int boff)
{
    char* base = sm + st * STG_STRIDE;
    cpa16(base + arow * 48 + akb,        Ag0 + k0);
    cpa16(base + 6144 + arow * 48 + akb, Ag1 + k0);
    cpa16(base + boff + brow * 48 + bkb, Bg + k0);
    cpa_commit();
}

__device__ __forceinline__ void gemm_bf16_body(
    const __nv_bfloat16* __restrict__ Ahg, const __nv_bfloat16* __restrict__ Alg,
    const __nv_bfloat16* __restrict__ Bhg, const __nv_bfloat16* __restrict__ Blg,
    float* __restrict__ C, int M, int N, int K, int bx, int by, char* sm)
{
    const int tid  = threadIdx.x;
    const int m0   = by * 128;
    const int n0   = bx * 64;
    const int wid  = tid >> 5;
    const int lane = tid & 31;
    const int gid  = lane >> 2;
    const int tig  = lane & 3;
    const int wm   = (wid & 3) * 32;
    const int wn   = (wid >> 2) * 32;
    const int g8   = lane >> 3;      // ldmatrix tile group 0..3
    const int r8   = lane & 7;       // row within tile

    // producers
    const int arow = tid >> 1, akb = (tid & 1) * 16, ak = (tid & 1) * 8;
    const int bt = tid & 127;
    const int brow = bt >> 1, bkb = (bt & 1) * 16, bk = (bt & 1) * 8;
    const bool bhi = tid < 128;
    const int boff = bhi ? 12288 : 15360;

    const __nv_bfloat16* Ag0 = Ahg + (size_t)(m0 + arow) * K + ak;
    const __nv_bfloat16* Ag1 = Alg + (size_t)(m0 + arow) * K + ak;
    const __nv_bfloat16* Bg  = (bhi ? Bhg : Blg) + (size_t)(n0 + brow) * K + bk;

    float acc[2][4][4];
    #pragma unroll
    for (int mt = 0; mt < 2; mt++)
        #pragma unroll
        for (int nt = 0; nt < 4; nt++)
            #pragma unroll
            for (int r = 0; r < 4; r++) acc[mt][nt][r] = 0.0f;

    // ldmatrix lane addressing (precompute byte offsets within stage)
    const int a_row = wm + (g8 & 1) * 8 + r8;          // + mt*16
    const int a_col = (g8 >> 1) * 16;                   // bytes
    const int b_row = wn + (g8 >> 1) * 8 + r8;          // + pair*16
    const int b_col = (g8 & 1) * 16;                    // bytes

    const int NC = K >> 4;
    issue_chunk(sm, 0, 0,  Ag0, Ag1, Bg, arow, akb, brow, bkb, boff);
    issue_chunk(sm, 1, 16, Ag0, Ag1, Bg, arow, akb, brow, bkb, boff);

    for (int i = 0; i < NC; i++) {
        const int st = i % 3;
        if (i + 2 < NC) cpa_wait<1>(); else cpa_wait<0>();
        __syncthreads();
        if (i + 2 < NC)
            issue_chunk(sm, (i + 2) % 3, (i + 2) * 16,
                        Ag0, Ag1, Bg, arow, akb, brow, bkb, boff);

        char* base = sm + st * STG_STRIDE;
        unsigned int afh[2][4], afl[2][4], bfh[4][2], bfl[4][2];
        #pragma unroll
        for (int mt = 0; mt < 2; mt++) {
            const int ro = (a_row + mt * 16) * 48 + a_col;
            ldsm4(afh[mt][0], afh[mt][1], afh[mt][2], afh[mt][3], base + ro);
            ldsm4(afl[mt][0], afl[mt][1], afl[mt][2], afl[mt][3], base + 6144 + ro);
        }
        #pragma unroll
        for (int p = 0; p < 2; p++) {
            const int ro = (b_row + p * 16) * 48 + b_col;
            ldsm4(bfh[p*2][0], bfh[p*2][1], bfh[p*2+1][0], bfh[p*2+1][1],
                  base + 12288 + ro);
            ldsm4(bfl[p*2][0], bfl[p*2][1], bfl[p*2+1][0], bfl[p*2+1][1],
                  base + 15360 + ro);
        }
        #pragma unroll
        for (int mt = 0; mt < 2; mt++)
            #pragma unroll
            for (int nt = 0; nt < 4; nt++) {
                mma16_bf16(acc[mt][nt], afh[mt], bfh[nt]);
                mma16_bf16(acc[mt][nt], afh[mt], bfl[nt]);
                mma16_bf16(acc[mt][nt], afl[mt], bfh[nt]);
            }
    }

    #pragma unroll
    for (int mt = 0; mt < 2; mt++)
        #pragma unroll
        for (int nt = 0; nt < 4; nt++) {
            const int r0 = m0 + wm + mt * 16 + gid;
            const int c0 = n0 + wn + nt * 8 + tig * 2;
            *(float2*)&C[(size_t)r0 * N + c0]       = make_float2(acc[mt][nt][0], acc[mt][nt][1]);
            *(float2*)&C[(size_t)(r0 + 8) * N + c0] = make_float2(acc[mt][nt][2], acc[mt][nt][3]);
        }
}

// ---------------------------------------------------------------------------
// ACCURATE fp32 router GEMM body (two-level chunked accumulation).
// Bit-identical math to the passing kernel — controls top-k flips.
// ---------------------------------------------------------------------------
template <bool GELU>
__device__ __forceinline__ void acc_body(
    const float* __restrict__ A, const float* __restrict__ B,
    float* __restrict__ C, int M, int N, int K, int bx, int by)
{
    __shared__ float As[8][128];
    __shared__ float Bs[8][64];

    const int m0 = by * 128;
    const int n0 = bx * 64;
    const int tid = threadIdx.x;
    const int lrA = tid >> 1;
    const int lcA = (tid & 1) * 4;
    const int lrB = tid >> 2;
    const int lcB = (tid & 3) * 2;
    const int tx = tid & 15;
    const int ty = tid >> 4;

    const float* Aptr = A + (size_t)(m0 + lrA) * K + lcA;
    const float* Bptr = B + (size_t)(n0 + lrB) * K + lcB;

    float acc[8][4], chk[8][4];
    #pragma unroll
    for (int i = 0; i < 8; i++)
        #pragma unroll
        for (int j = 0; j < 4; j++) { acc[i][j] = 0.0f; chk[i][j] = 0.0f; }

    float4 av = *(const float4*)(Aptr);
    float2 bv = *(const float2*)(Bptr);

    for (int k0 = 0; k0 < K; k0 += 8) {
        As[lcA + 0][lrA] = av.x; As[lcA + 1][lrA] = av.y;
        As[lcA + 2][lrA] = av.z; As[lcA + 3][lrA] = av.w;
        Bs[lcB + 0][lrB] = bv.x; Bs[lcB + 1][lrB] = bv.y;
        __syncthreads();

        if (k0 + 8 < K) {
            av = *(const float4*)(Aptr + k0 + 8);
            bv = *(const float2*)(Bptr + k0 + 8);
        }

        #pragma unroll
        for (int kk = 0; kk < 8; kk++) {
            float4 a0 = *(const float4*)&As[kk][ty * 4];
            float4 a1 = *(const float4*)&As[kk][64 + ty * 4];
            float4 b0 = *(const float4*)&Bs[kk][tx * 4];
            float ar[8] = {a0.x, a0.y, a0.z, a0.w, a1.x, a1.y, a1.z, a1.w};
            float br[4] = {b0.x, b0.y, b0.z, b0.w};
            #pragma unroll
            for (int i = 0; i < 8; i++)
                #pragma unroll
                for (int j = 0; j < 4; j++)
                    chk[i][j] = fmaf(ar[i], br[j], chk[i][j]);
        }
        if ((k0 & 24) == 24) {
            #pragma unroll
            for (int i = 0; i < 8; i++)
                #pragma unroll
                for (int j = 0; j < 4; j++) {
                    acc[i][j] = __fadd_rn(acc[i][j], chk[i][j]);
                    chk[i][j] = 0.0f;
                }
        }
        __syncthreads();
    }

    #pragma unroll
    for (int i = 0; i < 8; i++) {
        const int row = m0 + ((i < 4) ? (ty * 4 + i) : (64 + ty * 4 + i - 4));
        float4 r;
        float v0 = acc[i][0], v1 = acc[i][1], v2 = acc[i][2], v3 = acc[i][3];
        if (GELU) { v0 = gelu_f(v0); v1 = gelu_f(v1); v2 = gelu_f(v2); v3 = gelu_f(v3); }
        r.x = v0; r.y = v1; r.z = v2; r.w = v3;
        *(float4*)(C + (size_t)row * N + n0 + tx * 4) = r;
    }
}

// ---------------------------------------------------------------------------
// Kernels
// ---------------------------------------------------------------------------
template <bool GELU>
__global__ void __launch_bounds__(256) gemm_bt_acc(
    const float* __restrict__ A, const float* __restrict__ B,
    float* __restrict__ C, int M, int N, int K)
{
    acc_body<GELU>(A, B, C, M, N, K, blockIdx.x, blockIdx.y);
}

// Fused heterogeneous kernel: even bid -> fp32 scores block (fma pipe),
// odd bid -> bf16 z block (tensor pipe). Interleave keeps both pipes busy.
__global__ void __launch_bounds__(256) fused_scores_z(
    const float* __restrict__ h, const float* __restrict__ Wr2,
    float* __restrict__ sc,
    const __nv_bfloat16* __restrict__ xh, const __nv_bfloat16* __restrict__ xl,
    const __nv_bfloat16* __restrict__ w1h, const __nv_bfloat16* __restrict__ w1l,
    float* __restrict__ z)
{
    extern __shared__ __align__(16) char dynsm[];
    const int bid = blockIdx.x;
    const int sid = bid >> 1;
    const int bx = sid & 63;
    const int by = sid >> 6;
    if (bid & 1) {
        gemm_bf16_body(xh, xl, w1h, w1l, z, NROWS, DFF, DMODEL, bx, by, dynsm);
    } else {
        acc_body<false>(h, Wr2, sc, NROWS, DFF, DMODEL, bx, by);
    }
}

__global__ void __launch_bounds__(256) gemm_bt_bf16v2(
    const __nv_bfloat16* __restrict__ Ahg, const __nv_bfloat16* __restrict__ Alg,
    const __nv_bfloat16* __restrict__ Bhg, const __nv_bfloat16* __restrict__ Blg,
    float* __restrict__ C, int M, int N, int K)
{
    extern __shared__ __align__(16) char dynsm[];
    gemm_bf16_body(Ahg, Alg, Bhg, Blg, C, M, N, K, blockIdx.x, blockIdx.y, dynsm);
}

// ---------------------------------------------------------------------------
// Per-row exact top-k (radix select) + split(mask*gelu(z)) into bf16 hi/lo
// ---------------------------------------------------------------------------
__global__ void __launch_bounds__(256) topk_mask_gelu_split(
    const float* __restrict__ scores, const float* __restrict__ z,
    __nv_bfloat16* __restrict__ zh, __nv_bfloat16* __restrict__ zl)
{
    __shared__ unsigned int keys[DFF];
    __shared__ unsigned int hist[256];
    __shared__ unsigned char mask[DFF];

    const int row = blockIdx.x;
    const int tid = threadIdx.x;
    const float* srow = scores + (size_t)row * DFF;
    const float* zrow = z + (size_t)row * DFF;

    for (int j = tid; j < DFF; j += 256) {
        unsigned int u = __float_as_uint(srow[j]);
        u = (u & 0x80000000u) ? ~u : (u | 0x80000000u);
        keys[j] = u;
    }

    unsigned int prefix = 0, pmask = 0;
    int remaining = TOPK;
    int lastcnt = 0;

    #pragma unroll
    for (int p = 0; p < 4; p++) {
        const int shift = 24 - 8 * p;
        __syncthreads();
        if (tid < 256) hist[tid] = 0;
        __syncthreads();
        for (int j = tid; j < DFF; j += 256) {
            unsigned int k = keys[j];
            if ((k & pmask) == prefix)
                atomicAdd(&hist[(k >> shift) & 255u], 1u);
        }
        __syncthreads();
        int cum = 0, digit = 0;
        for (int bbin = 255; bbin >= 0; bbin--) {
            int c = (int)hist[bbin];
            if (cum + c >= remaining) { digit = bbin; lastcnt = c; break; }
            cum += c;
        }
        remaining -= cum;
        prefix |= ((unsigned int)digit) << shift;
        pmask  |= 0xFFu << shift;
    }
    const unsigned int T = prefix;

    __syncthreads();
    for (int j = tid; j < DFF; j += 256)
        mask[j] = (keys[j] > T) ? (unsigned char)1 : (unsigned char)0;

    if (lastcnt == remaining) {
        for (int j = tid; j < DFF; j += 256)
            if (keys[j] == T) mask[j] = 1;
    } else {
        __syncthreads();
        if (tid == 0) {
            int need = remaining;
            for (int j = 0; j < DFF && need > 0; j++)
                if (keys[j] == T) { mask[j] = 1; need--; }
        }
    }
    __syncthreads();

    for (int j = tid * 2; j < DFF; j += 512) {
        float v0 = mask[j]     ? gelu_f(zrow[j])     : 0.0f;
        float v1 = mask[j + 1] ? gelu_f(zrow[j + 1]) : 0.0f;
        unsigned int H, L;
        split2(v0, v1, H, L);
        *(unsigned int*)(zh + (size_t)row * DFF + j) = H;
        *(unsigned int*)(zl + (size_t)row * DFF + j) = L;
    }
}

// ---------------------------------------------------------------------------
// Launch
// Inputs: 0:x 1:W1 2:W2 3:W_router_1 4:W_router_2 5:ln_gamma 6:ln_beta 7:top_k
// ---------------------------------------------------------------------------
extern "C" void kernel_launch(void* const* d_in, const int* in_sizes, int n_in,
                              void* d_out, int out_size)
{
    const float* x    = (const float*)d_in[0];
    const float* W1   = (const float*)d_in[1];
    const float* W2   = (const float*)d_in[2];
    const float* Wr1  = (const float*)d_in[3];
    const float* Wr2  = (const float*)d_in[4];
    const float* gma  = (const float*)d_in[5];
    const float* bta  = (const float*)d_in[6];
    float* out = (float*)d_out;

    float *xn, *h, *sc, *z;
    __nv_bfloat16 *xh, *xl, *w1h, *w1l, *w2h, *w2l, *zh, *zl;
    cudaGetSymbolAddress((void**)&xn, g_xn);
    cudaGetSymbolAddress((void**)&h,  g_h);
    cudaGetSymbolAddress((void**)&sc, g_sc);
    cudaGetSymbolAddress((void**)&z,  g_z);
    cudaGetSymbolAddress((void**)&xh, g_xh);
    cudaGetSymbolAddress((void**)&xl, g_xl);
    cudaGetSymbolAddress((void**)&w1h, g_w1h);
    cudaGetSymbolAddress((void**)&w1l, g_w1l);
    cudaGetSymbolAddress((void**)&w2h, g_w2h);
    cudaGetSymbolAddress((void**)&w2l, g_w2l);
    cudaGetSymbolAddress((void**)&zh, g_zh);
    cudaGetSymbolAddress((void**)&zl, g_zl);

    cudaFuncSetAttribute(fused_scores_z, cudaFuncAttributeMaxDynamicSharedMemorySize, TC_DYNSMEM);
    cudaFuncSetAttribute(gemm_bt_bf16v2, cudaFuncAttributeMaxDynamicSharedMemorySize, TC_DYNSMEM);

    // 1) xn = LN(x)
    ln_kernel<<<NROWS, 256>>>(x, gma, bta, xn);

    // 1b) bf16 hi/lo splits
    split_bf16_kernel<<<2048, 256>>>(x,  xh,  xl,  (size_t)NROWS * DMODEL / 4);
    split_bf16_kernel<<<1024, 256>>>(W1, w1h, w1l, (size_t)DFF * DMODEL / 4);
    split_bf16_kernel<<<1024, 256>>>(W2, w2h, w2l, (size_t)DMODEL * DFF / 4);

    // 2) h = gelu(xn @ Wr1^T)   — accurate fp32 path (selection-critical)
    gemm_bt_acc<true><<<dim3(DMODEL / 64, NROWS / 128), 256>>>(xn, Wr1, h, NROWS, DMODEL, DMODEL);

    // 3+4) fused: scores = h @ Wr2^T (fp32, even blocks)
    //             z = x @ W1^T (bf16 3-term tensor, odd blocks) — pipe overlap
    fused_scores_z<<<16384, 256, TC_DYNSMEM>>>(h, Wr2, sc, xh, xl, w1h, w1l, z);

    // 5) top-512 per row; zh/zl = split(mask * gelu(z))
    topk_mask_gelu_split<<<NROWS, 256>>>(sc, z, zh, zl);

    // 6) out = z @ W2^T         — bf16 3-term tensor path v2
    gemm_bt_bf16v2<<<dim3(DMODEL / 64, NROWS / 128), 256, TC_DYNSMEM>>>(
        zh, zl, w2h, w2l, out, NROWS, DMODEL, DFF);
}

// round 9
// speedup vs baseline: 1.6827x; 1.3304x over previous
#include <cuda_runtime.h>
#include <cuda_bf16.h>
#include <stdint.h>
#include <cstdint>
#include <math.h>

#define NROWS 16384
#define DMODEL 1024
#define DFF 4096
#define TOPK 512

// Scratch (device globals)
__device__ float g_xn[(size_t)NROWS * DMODEL];
__device__ float g_h [(size_t)NROWS * DMODEL];
__device__ float g_sc[(size_t)NROWS * DFF];
__device__ float g_z [(size_t)NROWS * DFF];
__device__ __nv_bfloat16 g_xh [(size_t)NROWS * DMODEL];
__device__ __nv_bfloat16 g_xl [(size_t)NROWS * DMODEL];
__device__ __nv_bfloat16 g_hh [(size_t)NROWS * DMODEL];
__device__ __nv_bfloat16 g_hl [(size_t)NROWS * DMODEL];
__device__ __nv_bfloat16 g_w1h[(size_t)DFF * DMODEL];
__device__ __nv_bfloat16 g_w1l[(size_t)DFF * DMODEL];
__device__ __nv_bfloat16 g_w2h[(size_t)DMODEL * DFF];
__device__ __nv_bfloat16 g_w2l[(size_t)DMODEL * DFF];
__device__ __nv_bfloat16 g_wr2h[(size_t)DFF * DMODEL];
__device__ __nv_bfloat16 g_wr2l[(size_t)DFF * DMODEL];
__device__ __nv_bfloat16 g_zh [(size_t)NROWS * DFF];
__device__ __nv_bfloat16 g_zl [(size_t)NROWS * DFF];

// ---------------------------------------------------------------------------
// XLA f32 erf polynomial, uncontracted
// ---------------------------------------------------------------------------
__device__ __forceinline__ float erf_xla(float xin) {
    float x = fminf(fmaxf(xin, -4.0f), 4.0f);
    float x2 = __fmul_rn(x, x);
    float p = -2.72614225801306e-10f;
    p = __fadd_rn(__fmul_rn(p, x2),  2.77068142495902e-08f);
    p = __fadd_rn(__fmul_rn(p, x2), -2.10102402082508e-06f);
    p = __fadd_rn(__fmul_rn(p, x2), -5.69250639462346e-05f);
    p = __fadd_rn(__fmul_rn(p, x2), -7.34990630326855e-04f);
    p = __fadd_rn(__fmul_rn(p, x2), -2.95459980854025e-03f);
    p = __fadd_rn(__fmul_rn(p, x2), -1.60960333262415e-02f);
    float q = -1.45660718464996e-05f;
    q = __fadd_rn(__fmul_rn(q, x2), -2.13374055278905e-04f);
    q = __fadd_rn(__fmul_rn(q, x2), -1.68282697438203e-03f);
    q = __fadd_rn(__fmul_rn(q, x2), -7.37332916720468e-03f);
    q = __fadd_rn(__fmul_rn(q, x2), -1.42647390514189e-02f);
    return __fdiv_rn(__fmul_rn(x, p), q);
}

__device__ __forceinline__ float gelu_f(float v) {
    float t = __fdiv_rn(v, 1.41421356237309504880f);
    float e = erf_xla(t);
    return __fmul_rn(__fmul_rn(v, __fadd_rn(e, 1.0f)), 0.5f);
}

// ---------------------------------------------------------------------------
// LayerNorm (unchanged, passing)
// ---------------------------------------------------------------------------
__global__ void __launch_bounds__(256) ln_kernel(
    const float* __restrict__ x, const float* __restrict__ g,
    const float* __restrict__ b, float* __restrict__ o)
{
    __shared__ double red[8];
    __shared__ float s_mu, s_inv;
    const int row = blockIdx.x;
    const int tid = threadIdx.x;
    const float4* xr = (const float4*)(x + (size_t)row * DMODEL);
    float4* orow = (float4*)(o + (size_t)row * DMODEL);

    float4 v = xr[tid];

    double s = (double)v.x + (double)v.y + (double)v.z + (double)v.w;
    #pragma unroll
    for (int off = 16; off; off >>= 1) s += __shfl_down_sync(0xffffffffu, s, off);
    if ((tid & 31) == 0) red[tid >> 5] = s;
    __syncthreads();
    if (tid == 0) {
        double S = 0.0;
        #pragma unroll
        for (int w = 0; w < 8; w++) S += red[w];
        s_mu = (float)(S * (1.0 / DMODEL));
    }
    __syncthreads();
    const float mu = s_mu;
    __syncthreads();

    float dx0 = __fsub_rn(v.x, mu), dx1 = __fsub_rn(v.y, mu);
    float dx2 = __fsub_rn(v.z, mu), dx3 = __fsub_rn(v.w, mu);
    double ss = (double)__fmul_rn(dx0, dx0) + (double)__fmul_rn(dx1, dx1)
              + (double)__fmul_rn(dx2, dx2) + (double)__fmul_rn(dx3, dx3);
    #pragma unroll
    for (int off = 16; off; off >>= 1) ss += __shfl_down_sync(0xffffffffu, ss, off);
    if ((tid & 31) == 0) red[tid >> 5] = ss;
    __syncthreads();
    if (tid == 0) {
        double SS = 0.0;
        #pragma unroll
        for (int w = 0; w < 8; w++) SS += red[w];
        float var = (float)(SS * (1.0 / DMODEL));
        s_inv = (float)(1.0 / sqrt((double)__fadd_rn(var, 1e-5f)));
    }
    __syncthreads();
    const float inv = s_inv;
    const float4 gv = ((const float4*)g)[tid];
    const float4 bv = ((const float4*)b)[tid];
    float4 r;
    r.x = __fadd_rn(__fmul_rn(__fmul_rn(dx0, inv), gv.x), bv.x);
    r.y = __fadd_rn(__fmul_rn(__fmul_rn(dx1, inv), gv.y), bv.y);
    r.z = __fadd_rn(__fmul_rn(__fmul_rn(dx2, inv), gv.z), bv.z);
    r.w = __fadd_rn(__fmul_rn(__fmul_rn(dx3, inv), gv.w), bv.w);
    orow[tid] = r;
}

// ---------------------------------------------------------------------------
// fp32 -> bf16 hi/lo split
// ---------------------------------------------------------------------------
union bfu { __nv_bfloat162 b; unsigned int u; };

__device__ __forceinline__ void split2(float a, float b, unsigned int& hi, unsigned int& lo) {
    __nv_bfloat16 h0 = __float2bfloat16_rn(a);
    __nv_bfloat16 h1 = __float2bfloat16_rn(b);
    __nv_bfloat16 l0 = __float2bfloat16_rn(__fsub_rn(a, __bfloat162float(h0)));
    __nv_bfloat16 l1 = __float2bfloat16_rn(__fsub_rn(b, __bfloat162float(h1)));
    bfu H; H.b = __nv_bfloat162(h0, h1); hi = H.u;
    bfu L; L.b = __nv_bfloat162(l0, l1); lo = L.u;
}

__global__ void __launch_bounds__(256) split_bf16_kernel(
    const float* __restrict__ src, __nv_bfloat16* __restrict__ hi,
    __nv_bfloat16* __restrict__ lo, size_t n4)
{
    size_t i = (size_t)blockIdx.x * 256 + threadIdx.x;
    size_t stride = (size_t)gridDim.x * 256;
    for (; i < n4; i += stride) {
        float4 v = ((const float4*)src)[i];
        uint2 H, L;
        split2(v.x, v.y, H.x, L.x);
        split2(v.z, v.w, H.y, L.y);
        ((uint2*)hi)[i] = H;
        ((uint2*)lo)[i] = L;
    }
}

// ---------------------------------------------------------------------------
// mma / ldmatrix / cp.async primitives
// ---------------------------------------------------------------------------
__device__ __forceinline__ void mma16_bf16(float c[4], const unsigned int a[4],
                                           const unsigned int b[2]) {
    asm volatile("mma.sync.aligned.m16n8k16.row.col.f32.bf16.bf16.f32 "
        "{%0,%1,%2,%3}, {%4,%5,%6,%7}, {%8,%9}, {%0,%1,%2,%3};\n"
        : "+f"(c[0]), "+f"(c[1]), "+f"(c[2]), "+f"(c[3])
        : "r"(a[0]), "r"(a[1]), "r"(a[2]), "r"(a[3]), "r"(b[0]), "r"(b[1]));
}
__device__ __forceinline__ void ldsm4(unsigned int& r0, unsigned int& r1,
                                      unsigned int& r2, unsigned int& r3,
                                      const void* p) {
    unsigned int a = (unsigned int)__cvta_generic_to_shared(p);
    asm volatile("ldmatrix.sync.aligned.m8n8.x4.shared.b16 {%0,%1,%2,%3}, [%4];"
                 : "=r"(r0), "=r"(r1), "=r"(r2), "=r"(r3) : "r"(a));
}
__device__ __forceinline__ void cpa16(void* s, const void* g) {
    unsigned int a = (unsigned int)__cvta_generic_to_shared(s);
    asm volatile("cp.async.cg.shared.global [%0], [%1], 16;\n"
                 :: "r"(a), "l"(g) : "memory");
}
__device__ __forceinline__ void cpa_commit() {
    asm volatile("cp.async.commit_group;\n" ::: "memory");
}
template <int N>
__device__ __forceinline__ void cpa_wait() {
    asm volatile("cp.async.wait_group %0;\n" :: "n"(N) : "memory");
}

// ---------------------------------------------------------------------------
// bf16 3-term GEMM body (ldmatrix + cp.async, 3-stage) — unchanged, passing
// ---------------------------------------------------------------------------
#define STG_STRIDE 18432
#define TC_DYNSMEM (3 * STG_STRIDE)

__device__ __forceinline__ void issue_chunk(
    char* sm, int st, int k0,
    const __nv_bfloat16* Ag0, const __nv_bfloat16* Ag1, const __nv_bfloat16* Bg,
    int arow, int akb, int brow, int bkb, int boff)
{
    char* base = sm + st * STG_STRIDE;
    cpa16(base + arow * 48 + akb,        Ag0 + k0);
    cpa16(base + 6144 + arow * 48 + akb, Ag1 + k0);
    cpa16(base + boff + brow * 48 + bkb, Bg + k0);
    cpa_commit();
}

__device__ __forceinline__ void gemm_bf16_body(
    const __nv_bfloat16* __restrict__ Ahg, const __nv_bfloat16* __restrict__ Alg,
    const __nv_bfloat16* __restrict__ Bhg, const __nv_bfloat16* __restrict__ Blg,
    float* __restrict__ C, int M, int N, int K, int bx, int by, char* sm)
{
    const int tid  = threadIdx.x;
    const int m0   = by * 128;
    const int n0   = bx * 64;
    const int wid  = tid >> 5;
    const int lane = tid & 31;
    const int gid  = lane >> 2;
    const int tig  = lane & 3;
    const int wm   = (wid & 3) * 32;
    const int wn   = (wid >> 2) * 32;
    const int g8   = lane >> 3;
    const int r8   = lane & 7;

    const int arow = tid >> 1, akb = (tid & 1) * 16, ak = (tid & 1) * 8;
    const int bt = tid & 127;
    const int brow = bt >> 1, bkb = (bt & 1) * 16, bk = (bt & 1) * 8;
    const bool bhi = tid < 128;
    const int boff = bhi ? 12288 : 15360;

    const __nv_bfloat16* Ag0 = Ahg + (size_t)(m0 + arow) * K + ak;
    const __nv_bfloat16* Ag1 = Alg + (size_t)(m0 + arow) * K + ak;
    const __nv_bfloat16* Bg  = (bhi ? Bhg : Blg) + (size_t)(n0 + brow) * K + bk;

    float acc[2][4][4];
    #pragma unroll
    for (int mt = 0; mt < 2; mt++)
        #pragma unroll
        for (int nt = 0; nt < 4; nt++)
            #pragma unroll
            for (int r = 0; r < 4; r++) acc[mt][nt][r] = 0.0f;

    const int a_row = wm + (g8 & 1) * 8 + r8;
    const int a_col = (g8 >> 1) * 16;
    const int b_row = wn + (g8 >> 1) * 8 + r8;
    const int b_col = (g8 & 1) * 16;

    const int NC = K >> 4;
    issue_chunk(sm, 0, 0,  Ag0, Ag1, Bg, arow, akb, brow, bkb, boff);
    issue_chunk(sm, 1, 16, Ag0, Ag1, Bg, arow, akb, brow, bkb, boff);

    for (int i = 0; i < NC; i++) {
        const int st = i % 3;
        if (i + 2 < NC) cpa_wait<1>(); else cpa_wait<0>();
        __syncthreads();
        if (i + 2 < NC)
            issue_chunk(sm, (i + 2) % 3, (i + 2) * 16,
                        Ag0, Ag1, Bg, arow, akb, brow, bkb, boff);

        char* base = sm + st * STG_STRIDE;
        unsigned int afh[2][4], afl[2][4], bfh[4][2], bfl[4][2];
        #pragma unroll
        for (int mt = 0; mt < 2; mt++) {
            const int ro = (a_row + mt * 16) * 48 + a_col;
            ldsm4(afh[mt][0], afh[mt][1], afh[mt][2], afh[mt][3], base + ro);
            ldsm4(afl[mt][0], afl[mt][1], afl[mt][2], afl[mt][3], base + 6144 + ro);
        }
        #pragma unroll
        for (int p = 0; p < 2; p++) {
            const int ro = (b_row + p * 16) * 48 + b_col;
            ldsm4(bfh[p*2][0], bfh[p*2][1], bfh[p*2+1][0], bfh[p*2+1][1],
                  base + 12288 + ro);
            ldsm4(bfl[p*2][0], bfl[p*2][1], bfl[p*2+1][0], bfl[p*2+1][1],
                  base + 15360 + ro);
        }
        #pragma unroll
        for (int mt = 0; mt < 2; mt++)
            #pragma unroll
            for (int nt = 0; nt < 4; nt++) {
                mma16_bf16(acc[mt][nt], afh[mt], bfh[nt]);
                mma16_bf16(acc[mt][nt], afh[mt], bfl[nt]);
                mma16_bf16(acc[mt][nt], afl[mt], bfh[nt]);
            }
    }

    #pragma unroll
    for (int mt = 0; mt < 2; mt++)
        #pragma unroll
        for (int nt = 0; nt < 4; nt++) {
            const int r0 = m0 + wm + mt * 16 + gid;
            const int c0 = n0 + wn + nt * 8 + tig * 2;
            *(float2*)&C[(size_t)r0 * N + c0]       = make_float2(acc[mt][nt][0], acc[mt][nt][1]);
            *(float2*)&C[(size_t)(r0 + 8) * N + c0] = make_float2(acc[mt][nt][2], acc[mt][nt][3]);
        }
}

// ---------------------------------------------------------------------------
// fp32 chunked GEMM body for h, with gelu + bf16-split epilogue.
// Math bit-identical to the passing gemm_bt_acc<true>.
// ---------------------------------------------------------------------------
__device__ __forceinline__ void acc_body_h(
    const float* __restrict__ A, const float* __restrict__ B,
    float* __restrict__ C, __nv_bfloat16* __restrict__ Ch,
    __nv_bfloat16* __restrict__ Cl, int M, int N, int K, int bx, int by)
{
    __shared__ float As[8][128];
    __shared__ float Bs[8][64];

    const int m0 = by * 128;
    const int n0 = bx * 64;
    const int tid = threadIdx.x;
    const int lrA = tid >> 1;
    const int lcA = (tid & 1) * 4;
    const int lrB = tid >> 2;
    const int lcB = (tid & 3) * 2;
    const int tx = tid & 15;
    const int ty = tid >> 4;

    const float* Aptr = A + (size_t)(m0 + lrA) * K + lcA;
    const float* Bptr = B + (size_t)(n0 + lrB) * K + lcB;

    float acc[8][4], chk[8][4];
    #pragma unroll
    for (int i = 0; i < 8; i++)
        #pragma unroll
        for (int j = 0; j < 4; j++) { acc[i][j] = 0.0f; chk[i][j] = 0.0f; }

    float4 av = *(const float4*)(Aptr);
    float2 bv = *(const float2*)(Bptr);

    for (int k0 = 0; k0 < K; k0 += 8) {
        As[lcA + 0][lrA] = av.x; As[lcA + 1][lrA] = av.y;
        As[lcA + 2][lrA] = av.z; As[lcA + 3][lrA] = av.w;
        Bs[lcB + 0][lrB] = bv.x; Bs[lcB + 1][lrB] = bv.y;
        __syncthreads();

        if (k0 + 8 < K) {
            av = *(const float4*)(Aptr + k0 + 8);
            bv = *(const float2*)(Bptr + k0 + 8);
        }

        #pragma unroll
        for (int kk = 0; kk < 8; kk++) {
            float4 a0 = *(const float4*)&As[kk][ty * 4];
            float4 a1 = *(const float4*)&As[kk][64 + ty * 4];
            float4 b0 = *(const float4*)&Bs[kk][tx * 4];
            float ar[8] = {a0.x, a0.y, a0.z, a0.w, a1.x, a1.y, a1.z, a1.w};
            float br[4] = {b0.x, b0.y, b0.z, b0.w};
            #pragma unroll
            for (int i = 0; i < 8; i++)
                #pragma unroll
                for (int j = 0; j < 4; j++)
                    chk[i][j] = fmaf(ar[i], br[j], chk[i][j]);
        }
        if ((k0 & 24) == 24) {
            #pragma unroll
            for (int i = 0; i < 8; i++)
                #pragma unroll
                for (int j = 0; j < 4; j++) {
                    acc[i][j] = __fadd_rn(acc[i][j], chk[i][j]);
                    chk[i][j] = 0.0f;
                }
        }
        __syncthreads();
    }

    #pragma unroll
    for (int i = 0; i < 8; i++) {
        const int row = m0 + ((i < 4) ? (ty * 4 + i) : (64 + ty * 4 + i - 4));
        float v0 = gelu_f(acc[i][0]), v1 = gelu_f(acc[i][1]);
        float v2 = gelu_f(acc[i][2]), v3 = gelu_f(acc[i][3]);
        float4 r; r.x = v0; r.y = v1; r.z = v2; r.w = v3;
        *(float4*)(C + (size_t)row * N + n0 + tx * 4) = r;
        unsigned int H0, L0, H1, L1;
        split2(v0, v1, H0, L0);
        split2(v2, v3, H1, L1);
        uint2 H; H.x = H0; H.y = H1;
        uint2 L; L.x = L0; L.y = L1;
        *(uint2*)(Ch + (size_t)row * N + n0 + tx * 4) = H;
        *(uint2*)(Cl + (size_t)row * N + n0 + tx * 4) = L;
    }
}

// ---------------------------------------------------------------------------
// Fused heterogeneous kernel: 1/5 of blocks -> h (fp32 fma pipe),
// 4/5 -> z (bf16 tensor pipe). Independent computations.
// ---------------------------------------------------------------------------
__global__ void __launch_bounds__(256) fused_h_z(
    const float* __restrict__ xn, const float* __restrict__ Wr1,
    float* __restrict__ h, __nv_bfloat16* __restrict__ hh, __nv_bfloat16* __restrict__ hl,
    const __nv_bfloat16* __restrict__ xh, const __nv_bfloat16* __restrict__ xl,
    const __nv_bfloat16* __restrict__ w1h, const __nv_bfloat16* __restrict__ w1l,
    float* __restrict__ z)
{
    extern __shared__ __align__(16) char dynsm[];
    const int bid = blockIdx.x;
    if (bid % 5 == 0) {
        const int sid = bid / 5;               // 0..2047
        acc_body_h(xn, Wr1, h, hh, hl, NROWS, DMODEL, DMODEL, sid & 15, sid >> 4);
    } else {
        const int sid = bid - bid / 5 - 1;     // 0..8191
        gemm_bf16_body(xh, xl, w1h, w1l, z, NROWS, DFF, DMODEL, sid & 63, sid >> 6, dynsm);
    }
}

__global__ void __launch_bounds__(256) gemm_bt_bf16v2(
    const __nv_bfloat16* __restrict__ Ahg, const __nv_bfloat16* __restrict__ Alg,
    const __nv_bfloat16* __restrict__ Bhg, const __nv_bfloat16* __restrict__ Blg,
    float* __restrict__ C, int M, int N, int K)
{
    extern __shared__ __align__(16) char dynsm[];
    gemm_bf16_body(Ahg, Alg, Bhg, Blg, C, M, N, K, blockIdx.x, blockIdx.y, dynsm);
}

// ---------------------------------------------------------------------------
// Hybrid top-k: radix-select threshold on FAST scores, margin-band exact
// rescore (bit-identical chunked fp32), then split(mask*gelu(z)).
// ---------------------------------------------------------------------------
__device__ __forceinline__ unsigned int key_map(float f) {
    unsigned int u = __float_as_uint(f);
    return (u & 0x80000000u) ? ~u : (u | 0x80000000u);
}
__device__ __forceinline__ float key_unmap(unsigned int k) {
    unsigned int u = (k & 0x80000000u) ? (k ^ 0x80000000u) : ~k;
    return __uint_as_float(u);
}

#define CAND_CAP 128

__global__ void __launch_bounds__(256) topk_hybrid(
    const float* __restrict__ sc_fast, const float* __restrict__ h,
    const float* __restrict__ Wr2, const float* __restrict__ z,
    __nv_bfloat16* __restrict__ zh, __nv_bfloat16* __restrict__ zl)
{
    __shared__ unsigned int keys[DFF];
    __shared__ unsigned int hist[256];
    __shared__ unsigned char mask[DFF];
    __shared__ int s_nhi, s_ncand;
    __shared__ int s_cidx[CAND_CAP];
    __shared__ float s_cex[CAND_CAP];

    const int row = blockIdx.x;
    const int tid = threadIdx.x;
    const int wid = tid >> 5;
    const int lid = tid & 31;
    const float* srow = sc_fast + (size_t)row * DFF;
    const float* zrow = z + (size_t)row * DFF;
    const float* hrow = h + (size_t)row * DMODEL;

    if (tid == 0) { s_nhi = 0; s_ncand = 0; }
    for (int j = tid; j < DFF; j += 256)
        keys[j] = key_map(srow[j]);

    // radix select: 512th-largest fast key
    unsigned int prefix = 0, pmask = 0;
    int remaining = TOPK;
    #pragma unroll
    for (int p = 0; p < 4; p++) {
        const int shift = 24 - 8 * p;
        __syncthreads();
        if (tid < 256) hist[tid] = 0;
        __syncthreads();
        for (int j = tid; j < DFF; j += 256) {
            unsigned int k = keys[j];
            if ((k & pmask) == prefix)
                atomicAdd(&hist[(k >> shift) & 255u], 1u);
        }
        __syncthreads();
        int cum = 0, digit = 0;
        for (int bbin = 255; bbin >= 0; bbin--) {
            int c = (int)hist[bbin];
            if (cum + c >= remaining) { digit = bbin; break; }
            cum += c;
        }
        remaining -= cum;
        prefix |= ((unsigned int)digit) << shift;
        pmask  |= 0xFFu << shift;
    }
    const unsigned int T = prefix;
    const float Tf = key_unmap(T);
    const float M = fmaxf(1e-4f, 3e-4f * fabsf(Tf));
    const unsigned int hiK = key_map(Tf + M);
    const unsigned int loK = key_map(Tf - M);

    __syncthreads();
    // classify
    for (int j = tid; j < DFF; j += 256) {
        unsigned int k = keys[j];
        if (k > hiK) {
            mask[j] = 1;
            atomicAdd(&s_nhi, 1);
        } else {
            mask[j] = 0;
            if (k >= loK) {
                int pos = atomicAdd(&s_ncand, 1);
                if (pos < CAND_CAP) s_cidx[pos] = j;
            }
        }
    }
    __syncthreads();

    const int ncand = min(s_ncand, CAND_CAP);
    // exact rescore of band candidates: bit-identical chunked fp32
    // (lane l = chunk l: 32 sequential fmaf; fold chunks in order via fadd)
    for (int c = wid; c < ncand; c += 8) {
        const int j = s_cidx[c];
        const float* wrow = Wr2 + (size_t)j * DMODEL;
        const int kb = lid * 32;
        float chk = 0.0f;
        #pragma unroll 8
        for (int k = 0; k < 32; k++)
            chk = fmaf(hrow[kb + k], wrow[kb + k], chk);
        float acc = 0.0f;
        #pragma unroll
        for (int l = 0; l < 32; l++) {
            float v = __shfl_sync(0xffffffffu, chk, l);
            acc = __fadd_rn(acc, v);
        }
        if (lid == 0) s_cex[c] = acc;
    }
    __syncthreads();

    // thread 0: pick (512 - n_hi) best candidates by (exact desc, idx asc)
    if (tid == 0) {
        int slots = TOPK - s_nhi;
        if (slots > ncand) slots = ncand;
        bool used[CAND_CAP];
        for (int c = 0; c < ncand; c++) used[c] = false;
        for (int sIt = 0; sIt < slots; sIt++) {
            int best = -1;
            for (int c = 0; c < ncand; c++) {
                if (used[c]) continue;
                if (best < 0 || s_cex[c] > s_cex[best] ||
                    (s_cex[c] == s_cex[best] && s_cidx[c] < s_cidx[best]))
                    best = c;
            }
            used[best] = true;
            mask[s_cidx[best]] = 1;
        }
    }
    __syncthreads();

    for (int j = tid * 2; j < DFF; j += 512) {
        float v0 = mask[j]     ? gelu_f(zrow[j])     : 0.0f;
        float v1 = mask[j + 1] ? gelu_f(zrow[j + 1]) : 0.0f;
        unsigned int H, L;
        split2(v0, v1, H, L);
        *(unsigned int*)(zh + (size_t)row * DFF + j) = H;
        *(unsigned int*)(zl + (size_t)row * DFF + j) = L;
    }
}

// ---------------------------------------------------------------------------
// Launch
// Inputs: 0:x 1:W1 2:W2 3:W_router_1 4:W_router_2 5:ln_gamma 6:ln_beta 7:top_k
// ---------------------------------------------------------------------------
extern "C" void kernel_launch(void* const* d_in, const int* in_sizes, int n_in,
                              void* d_out, int out_size)
{
    const float* x    = (const float*)d_in[0];
    const float* W1   = (const float*)d_in[1];
    const float* W2   = (const float*)d_in[2];
    const float* Wr1  = (const float*)d_in[3];
    const float* Wr2  = (const float*)d_in[4];
    const float* gma  = (const float*)d_in[5];
    const float* bta  = (const float*)d_in[6];
    float* out = (float*)d_out;

    float *xn, *h, *sc, *z;
    __nv_bfloat16 *xh, *xl, *hh, *hl, *w1h, *w1l, *w2h, *w2l, *wr2h, *wr2l, *zh, *zl;
    cudaGetSymbolAddress((void**)&xn, g_xn);
    cudaGetSymbolAddress((void**)&h,  g_h);
    cudaGetSymbolAddress((void**)&sc, g_sc);
    cudaGetSymbolAddress((void**)&z,  g_z);
    cudaGetSymbolAddress((void**)&xh, g_xh);
    cudaGetSymbolAddress((void**)&xl, g_xl);
    cudaGetSymbolAddress((void**)&hh, g_hh);
    cudaGetSymbolAddress((void**)&hl, g_hl);
    cudaGetSymbolAddress((void**)&w1h, g_w1h);
    cudaGetSymbolAddress((void**)&w1l, g_w1l);
    cudaGetSymbolAddress((void**)&w2h, g_w2h);
    cudaGetSymbolAddress((void**)&w2l, g_w2l);
    cudaGetSymbolAddress((void**)&wr2h, g_wr2h);
    cudaGetSymbolAddress((void**)&wr2l, g_wr2l);
    cudaGetSymbolAddress((void**)&zh, g_zh);
    cudaGetSymbolAddress((void**)&zl, g_zl);

    cudaFuncSetAttribute(fused_h_z, cudaFuncAttributeMaxDynamicSharedMemorySize, TC_DYNSMEM);
    cudaFuncSetAttribute(gemm_bt_bf16v2, cudaFuncAttributeMaxDynamicSharedMemorySize, TC_DYNSMEM);

    // 1) xn = LN(x)
    ln_kernel<<<NROWS, 256>>>(x, gma, bta, xn);

    // 1b) bf16 hi/lo splits
    split_bf16_kernel<<<2048, 256>>>(x,   xh,   xl,   (size_t)NROWS * DMODEL / 4);
    split_bf16_kernel<<<1024, 256>>>(W1,  w1h,  w1l,  (size_t)DFF * DMODEL / 4);
    split_bf16_kernel<<<1024, 256>>>(W2,  w2h,  w2l,  (size_t)DMODEL * DFF / 4);
    split_bf16_kernel<<<1024, 256>>>(Wr2, wr2h, wr2l, (size_t)DFF * DMODEL / 4);

    // 2) fused: h = gelu(xn@Wr1^T) fp32 (fma pipe, + bf16 split epilogue)
    //           z = x@W1^T bf16 3-term (tensor pipe)
    fused_h_z<<<10240, 256, TC_DYNSMEM>>>(xn, Wr1, h, hh, hl, xh, xl, w1h, w1l, z);

    // 3) fast scores = h @ Wr2^T (bf16 3-term tensor path)
    gemm_bt_bf16v2<<<dim3(DFF / 64, NROWS / 128), 256, TC_DYNSMEM>>>(
        hh, hl, wr2h, wr2l, sc, NROWS, DFF, DMODEL);

    // 4) hybrid top-512: fast filter + exact margin-band rescore; split z
    topk_hybrid<<<NROWS, 256>>>(sc, h, Wr2, z, zh, zl);

    // 5) out = z @ W2^T (bf16 3-term tensor path)
    gemm_bt_bf16v2<<<dim3(DMODEL / 64, NROWS / 128), 256, TC_DYNSMEM>>>(
        zh, zl, w2h, w2l, out, NROWS, DMODEL, DFF);
}